// round 12
// baseline (speedup 1.0000x reference)
#include <cuda_runtime.h>
#include <cstdint>

#define BB 32
#define NPIX 16384
#define WIDTH 64

typedef unsigned long long u64;

__device__ __forceinline__ u64 pk(float lo, float hi) {
    u64 r; asm("mov.b64 %0, {%1, %2};" : "=l"(r) : "f"(lo), "f"(hi)); return r;
}
__device__ __forceinline__ u64 pk2(float v) {
    u64 r; asm("mov.b64 %0, {%1, %1};" : "=l"(r) : "f"(v)); return r;
}
__device__ __forceinline__ void fma2(u64& d, u64 a, u64 b) {
    asm("fma.rn.f32x2 %0, %1, %2, %0;" : "+l"(d) : "l"(a), "l"(b));
}
__device__ __forceinline__ void unpk(u64 v, float& lo, float& hi) {
    asm("mov.b64 {%0, %1}, %2;" : "=f"(lo), "=f"(hi) : "l"(v));
}
__device__ __forceinline__ uint32_t f2tf32(float v) {
    uint32_t r; asm("cvt.rna.tf32.f32 %0, %1;" : "=r"(r) : "f"(v)); return r;
}
__device__ __forceinline__ float tanh_fast(float x) {
    float r; asm("tanh.approx.f32 %0, %1;" : "=f"(r) : "f"(x)); return r;
}
// accurate fast tanh: 1 - 2/(exp2(2x*log2e)+1); MUFU-based, abs err ~3e-7
__device__ __forceinline__ float tanh_e(float x) {
    float e, r;
    asm("ex2.approx.f32 %0, %1;" : "=f"(e) : "f"(x * 2.8853900817779268f));
    asm("rcp.approx.f32 %0, %1;" : "=f"(r) : "f"(e + 1.0f));
    return 1.0f - 2.0f * r;
}
#define MMA_TF32(c0,c1,c2,c3,a0,a1,a2,a3,b0,b1) \
    asm volatile("mma.sync.aligned.m16n8k8.row.col.f32.tf32.tf32.f32 " \
        "{%0,%1,%2,%3}, {%4,%5,%6,%7}, {%8,%9}, {%0,%1,%2,%3};" \
        : "+f"(c0), "+f"(c1), "+f"(c2), "+f"(c3) \
        : "r"(a0), "r"(a1), "r"(a2), "r"(a3), "r"(b0), "r"(b1))

// ---------------- scratch ----------------
__device__ float g_x [ (size_t)BB*WIDTH*NPIX ];
__device__ float g_x1[ (size_t)BB*WIDTH*NPIX ];
__device__ float g_x2[ (size_t)BB*WIDTH*NPIX ];
__device__ float g_y1[ (size_t)BB*WIDTH*5120 ];
__device__ float g_z [ (size_t)BB*WIDTH*1600 ];
__device__ float g_zo[ (size_t)BB*WIDTH*1600 ];
__device__ float g_Tf  [40*128];
__device__ float g_TfT [128*40];
__device__ float2 g_ThP[40*128];
__device__ float g_TfThi[128*40], g_TfTlo[128*40];
__device__ float g_Ghi[40*128],  g_Glo[40*128];
__device__ float g_wT[(size_t)4*2*2*400*4096];
__device__ float g_cwT[4*9*64*64];

// gelu with HW tanh.approx (lift/final MLPs only)
__device__ __forceinline__ float gelu_t(float x) {
    float x3 = x * x * x;
    return 0.5f * x * (1.0f + tanh_fast(0.7978845608028654f * (x + 0.044715f * x3)));
}

__global__ void k_init_tables() {
    for (int i = threadIdx.x + blockIdx.x * blockDim.x; i < 40 * 128; i += blockDim.x * gridDim.x) {
        int k = i / 128, w = i % 128;
        float s, c, tf;
        if (k < 20) { sincospif((float)((w * k) & 127) / 64.0f, &s, &c); tf = c; }
        else        { sincospif((float)((w * (k - 20)) & 127) / 64.0f, &s, &c); tf = -s; }
        g_Tf[i] = tf;
        g_TfT[w * 40 + k] = tf;
        uint32_t hb = f2tf32(tf);
        float hv = __uint_as_float(hb);
        g_TfThi[w * 40 + k] = hv;
        g_TfTlo[w * 40 + k] = __uint_as_float(f2tf32(tf - hv));
        int kxv = (k < 20) ? k : (108 + (k - 20));
        sincospif((float)((w * kxv) & 127) / 64.0f, &s, &c);
        g_ThP[i] = make_float2(c, s);
        const float inv = 1.0f / 16384.0f;
        float gv;
        if (k == 0)       gv = inv;
        else if (k < 20)  { sincospif((float)((w * k) & 127) / 64.0f, &s, &c); gv = 2.0f * inv * c; }
        else if (k == 20) gv = 0.0f;
        else              { sincospif((float)((w * (k - 20)) & 127) / 64.0f, &s, &c); gv = -2.0f * inv * s; }
        uint32_t gb = f2tf32(gv);
        float gh = __uint_as_float(gb);
        g_Ghi[k * 128 + w] = gh;
        g_Glo[k * 128 + w] = __uint_as_float(f2tf32(gv - gh));
    }
}

// ---------------- one-time spectral weight transpose ----------------
__global__ void k_wt(const float* __restrict__ sw1r, const float* __restrict__ sw1i,
                     const float* __restrict__ sw2r, const float* __restrict__ sw2i)
{
    __shared__ float t[32][33];
    int lqc = blockIdx.z;
    int l = lqc >> 2, q = (lqc >> 1) & 1, c = lqc & 1;
    const float* src = (c == 0) ? (q ? sw2r : sw1r) : (q ? sw2i : sw1i);
    src += (size_t)l * 1638400;
    int c0 = blockIdx.x * 32, r0 = blockIdx.y * 32;
    for (int j = threadIdx.y; j < 32; j += 8) {
        int col = c0 + threadIdx.x;
        if (col < 400) t[j][threadIdx.x] = src[(size_t)(r0 + j) * 400 + col];
    }
    __syncthreads();
    float* dst = g_wT + (size_t)lqc * 400 * 4096;
    for (int j = threadIdx.y; j < 32; j += 8) {
        int col = c0 + j;
        if (col < 400) dst[(size_t)col * 4096 + r0 + threadIdx.x] = t[threadIdx.x][j];
    }
}

// ---------------- one-time conv weight transpose + tf32 round ----------------
__global__ void k_cwt(const float* __restrict__ cw) {
    int i = blockIdx.x * 256 + threadIdx.x;
    if (i >= 4 * 9 * 64 * 64) return;
    int o = i & 63; int rem = i >> 6;
    int c = rem & 63; rem >>= 6;
    int tap = rem % 9; int l = rem / 9;
    float v = cw[(((size_t)l * 64 + o) * 64 + c) * 9 + tap];
    g_cwT[((size_t)(l * 9 + tap) * 64 + c) * 64 + o] = __uint_as_float(f2tf32(v));
}

// ---------------- lift: 2 pixels/thread ----------------
__global__ void __launch_bounds__(128) k_lift(
    const float* __restrict__ xin, const float* __restrict__ qa, const float* __restrict__ qb,
    const float* __restrict__ w1, const float* __restrict__ b1,
    const float* __restrict__ w2, const float* __restrict__ b2)
{
    __shared__ float qas[48], qbs[48], b2s[48];
    __shared__ __align__(16) float w1s[128 * 16];
    __shared__ float b1s[128];
    __shared__ __align__(16) float w2t[128 * 48];
    int tid = threadIdx.x;
    if (tid < 48) { qas[tid] = qa[tid]; qbs[tid] = qb[tid]; b2s[tid] = b2[tid]; }
    b1s[tid] = b1[tid];
    for (int i = tid; i < 2048; i += 128) w1s[i] = w1[i];
    for (int i = tid; i < 6144; i += 128) { int o = i / 128, m = i % 128; w2t[m * 48 + o] = w2[i]; }
    __syncthreads();
    int p0 = blockIdx.x * 256 + tid;
    int b = p0 >> 14, pix0 = p0 & 16383;
    int h0 = pix0 >> 7, w0 = pix0 & 127;
    int h1 = h0 + 1;
    float f0[16], f1[16];
    const float* xp = xin + ((size_t)b * 10) * NPIX + pix0;
#pragma unroll
    for (int c = 0; c < 10; c++) { f0[c] = xp[(size_t)c * NPIX]; f1[c] = xp[(size_t)c * NPIX + 128]; }
    f0[10] = (float)h0 * (1.0f / 127.0f);  f1[10] = (float)h1 * (1.0f / 127.0f);
    f0[11] = (float)w0 * (1.0f / 127.0f);  f1[11] = f0[11];
#pragma unroll
    for (int j = 0; j < 4; j++) {
        float sa0 = 0.f, sb0 = 0.f, sa1 = 0.f, sb1 = 0.f;
#pragma unroll
        for (int c = 0; c < 12; c++) {
            float wa = qas[j * 12 + c], wb = qbs[j * 12 + c];
            sa0 += wa * f0[c]; sb0 += wb * f0[c];
            sa1 += wa * f1[c]; sb1 += wb * f1[c];
        }
        f0[12 + j] = sa0 * sb0;
        f1[12 + j] = sa1 * sb1;
    }
    u64 acc0[24], acc1[24];
#pragma unroll
    for (int q = 0; q < 24; q++) {
        u64 v = pk(b2s[2 * q], b2s[2 * q + 1]);
        acc0[q] = v; acc1[q] = v;
    }
    for (int m = 0; m < 128; m++) {
        float t0 = b1s[m], t1 = t0;
#pragma unroll
        for (int c = 0; c < 16; c++) {
            float wv = w1s[m * 16 + c];
            t0 += wv * f0[c];
            t1 += wv * f1[c];
        }
        u64 g20 = pk2(gelu_t(t0));
        u64 g21 = pk2(gelu_t(t1));
        const float* wr = &w2t[m * 48];
#pragma unroll
        for (int q4 = 0; q4 < 12; q4++) {
            ulonglong2 wv = *(const ulonglong2*)&wr[q4 * 4];
            fma2(acc0[q4 * 2],     wv.x, g20); fma2(acc0[q4 * 2 + 1], wv.y, g20);
            fma2(acc1[q4 * 2],     wv.x, g21); fma2(acc1[q4 * 2 + 1], wv.y, g21);
        }
    }
    float* op = g_x + ((size_t)b * WIDTH) * NPIX + pix0;
#pragma unroll
    for (int c = 0; c < 16; c++) {
        op[(size_t)c * NPIX]       = f0[c];
        op[(size_t)c * NPIX + 128] = f1[c];
    }
#pragma unroll
    for (int q = 0; q < 24; q++) {
        float lo, hi;
        unpk(acc0[q], lo, hi);
        op[(size_t)(16 + 2 * q) * NPIX] = lo;
        op[(size_t)(17 + 2 * q) * NPIX] = hi;
        unpk(acc1[q], lo, hi);
        op[(size_t)(16 + 2 * q) * NPIX + 128] = lo;
        op[(size_t)(17 + 2 * q) * NPIX + 128] = hi;
    }
}

// ---------------- fwd rfft along W via tf32 MMA (3-term split) ----------------
__global__ void __launch_bounds__(256) k_fwdW_mma() {
    __shared__ float xs_hi[32 * 133], xs_lo[32 * 133];
    int tid = threadIdx.x;
    int lane = tid & 31, warp = tid >> 5;
    int tig = lane & 3, gid = lane >> 2;
    size_t pbase = (size_t)blockIdx.x * 128 * 128;
    float acc[5][4];
#pragma unroll
    for (int nf = 0; nf < 5; nf++)
#pragma unroll
        for (int r = 0; r < 4; r++) acc[nf][r] = 0.f;

    for (int wc = 0; wc < 4; wc++) {
        __syncthreads();
        for (int i = tid; i < 4096; i += 256) {
            int row = i >> 5, wl = i & 31;
            float v = g_x[pbase + (size_t)row * 128 + wc * 32 + wl];
            uint32_t hb = f2tf32(v);
            float hv = __uint_as_float(hb);
            xs_hi[wl * 133 + row] = hv;
            xs_lo[wl * 133 + row] = __uint_as_float(f2tf32(v - hv));
        }
        __syncthreads();
#pragma unroll
        for (int k8 = 0; k8 < 4; k8++) {
            const uint32_t* ah = (const uint32_t*)&xs_hi[(k8 * 8 + tig) * 133 + warp * 16 + gid];
            const uint32_t* al = (const uint32_t*)&xs_lo[(k8 * 8 + tig) * 133 + warp * 16 + gid];
            uint32_t ah0 = ah[0], ah1 = ah[8], ah2 = ah[4 * 133], ah3 = ah[4 * 133 + 8];
            uint32_t al0 = al[0], al1 = al[8], al2 = al[4 * 133], al3 = al[4 * 133 + 8];
            int kglob = wc * 32 + k8 * 8 + tig;
#pragma unroll
            for (int nf = 0; nf < 5; nf++) {
                const uint32_t* bh = (const uint32_t*)&g_TfThi[kglob * 40 + nf * 8 + gid];
                const uint32_t* bl = (const uint32_t*)&g_TfTlo[kglob * 40 + nf * 8 + gid];
                uint32_t bh0 = __ldg(bh), bh1 = __ldg(bh + 4 * 40);
                uint32_t bl0 = __ldg(bl), bl1 = __ldg(bl + 4 * 40);
                MMA_TF32(acc[nf][0], acc[nf][1], acc[nf][2], acc[nf][3],
                         ah0, ah1, ah2, ah3, bh0, bh1);
                MMA_TF32(acc[nf][0], acc[nf][1], acc[nf][2], acc[nf][3],
                         al0, al1, al2, al3, bh0, bh1);
                MMA_TF32(acc[nf][0], acc[nf][1], acc[nf][2], acc[nf][3],
                         ah0, ah1, ah2, ah3, bl0, bl1);
            }
        }
    }
    size_t row0 = (size_t)blockIdx.x * 128 + warp * 16 + gid;
#pragma unroll
    for (int nf = 0; nf < 5; nf++) {
        int n = nf * 8 + 2 * tig;
        *(float2*)&g_y1[row0 * 40 + n]       = make_float2(acc[nf][0], acc[nf][1]);
        *(float2*)&g_y1[(row0 + 8) * 40 + n] = make_float2(acc[nf][2], acc[nf][3]);
    }
}

// ---------------- fwd DFT along H: complex-packed ----------------
__global__ void __launch_bounds__(256) k_fwdH() {
    __shared__ __align__(16) float2 ysA[2560];
    __shared__ __align__(16) float2 ysB[2560];
    int tid = threadIdx.x;
    int bc = blockIdx.x;
    const float* src = g_y1 + (size_t)bc * 5120;
    for (int i = tid; i < 2560; i += 256) {
        int h = i / 20, ky = i - h * 20;
        float yr = src[h * 40 + ky], yi = src[h * 40 + 20 + ky];
        ysA[i] = make_float2(yr, yi);
        ysB[i] = make_float2(yi, -yr);
    }
    __syncthreads();
    if (tid < 200) {
        int kx0 = tid / 10, kyp = tid - (tid / 10) * 10;
        int kx1 = kx0 + 20, kyg = kyp * 2;
        u64 Z0 = pk(0.f, 0.f), Z1 = Z0, Z2 = Z0, Z3 = Z0;
#pragma unroll 4
        for (int h = 0; h < 128; h++) {
            float2 cs0 = __ldg(&g_ThP[kx0 * 128 + h]);
            float2 cs1 = __ldg(&g_ThP[kx1 * 128 + h]);
            u64 c0 = pk2(cs0.x), s0 = pk2(cs0.y);
            u64 c1 = pk2(cs1.x), s1 = pk2(cs1.y);
            ulonglong2 ya = *(const ulonglong2*)&ysA[h * 20 + kyg];
            ulonglong2 yb = *(const ulonglong2*)&ysB[h * 20 + kyg];
            fma2(Z0, ya.x, c0); fma2(Z0, yb.x, s0);
            fma2(Z1, ya.y, c0); fma2(Z1, yb.y, s0);
            fma2(Z2, ya.x, c1); fma2(Z2, yb.x, s1);
            fma2(Z3, ya.y, c1); fma2(Z3, yb.y, s1);
        }
        float zr, zi;
        size_t zb = (size_t)bc * 1600;
        unpk(Z0, zr, zi); g_z[zb + kx0 * 20 + kyg]     = zr; g_z[zb + 800 + kx0 * 20 + kyg]     = zi;
        unpk(Z1, zr, zi); g_z[zb + kx0 * 20 + kyg + 1] = zr; g_z[zb + 800 + kx0 * 20 + kyg + 1] = zi;
        unpk(Z2, zr, zi); g_z[zb + kx1 * 20 + kyg]     = zr; g_z[zb + 800 + kx1 * 20 + kyg]     = zi;
        unpk(Z3, zr, zi); g_z[zb + kx1 * 20 + kyg + 1] = zr; g_z[zb + 800 + kx1 * 20 + kyg + 1] = zi;
    }
}

// ---------------- per-mode complex channel mixing ----------------
__global__ void __launch_bounds__(256) k_mix(int layer)
{
    __shared__ __align__(16) float Wr[64 * 64], Wi[64 * 64];
    __shared__ float Zr[16 * 64], Zi[16 * 64];
    int tid = threadIdx.x;
    int mode = blockIdx.x;
    int kxi = mode / 20, ky = mode - kxi * 20;
    int q = (kxi < 20) ? 0 : 1;
    int kxm = (kxi < 20) ? kxi : kxi - 20;
    size_t col = (size_t)kxm * 20 + ky;
    const float* wrp = g_wT + (((size_t)(layer * 2 + q) * 2 + 0) * 400 + col) * 4096;
    const float* wip = g_wT + (((size_t)(layer * 2 + q) * 2 + 1) * 400 + col) * 4096;
    for (int i = tid; i < 4096; i += 256) {
        Wr[i] = wrp[i]; Wi[i] = wip[i];
    }
    int og = tid & 15, bb = tid >> 4;
    for (int pass = 0; pass < 2; pass++) {
        int b0 = pass * 16;
        __syncthreads();
        for (int i = tid; i < 1024; i += 256) {
            int lb = i >> 6, c = i & 63;
            size_t zb = ((size_t)(b0 + lb) * 64 + c) * 1600 + mode;
            Zr[i] = g_z[zb]; Zi[i] = g_z[zb + 800];
        }
        __syncthreads();
        float or0=0,or1=0,or2=0,or3=0, oi0=0,oi1=0,oi2=0,oi3=0;
#pragma unroll 8
        for (int i2 = 0; i2 < 64; i2++) {
            float zr = Zr[bb * 64 + i2], zi = Zi[bb * 64 + i2];
            float4 wr4 = *(const float4*)&Wr[i2 * 64 + og * 4];
            float4 wi4 = *(const float4*)&Wi[i2 * 64 + og * 4];
            or0 += zr * wr4.x - zi * wi4.x;  oi0 += zr * wi4.x + zi * wr4.x;
            or1 += zr * wr4.y - zi * wi4.y;  oi1 += zr * wi4.y + zi * wr4.y;
            or2 += zr * wr4.z - zi * wi4.z;  oi2 += zr * wi4.z + zi * wr4.z;
            or3 += zr * wr4.w - zi * wi4.w;  oi3 += zr * wi4.w + zi * wr4.w;
        }
        size_t ob = ((size_t)(b0 + bb) * 64 + og * 4) * 1600 + mode;
        g_zo[ob]        = or0;  g_zo[ob + 800]  = oi0;
        g_zo[ob + 1600] = or1;  g_zo[ob + 2400] = oi1;
        g_zo[ob + 3200] = or2;  g_zo[ob + 4000] = oi2;
        g_zo[ob + 4800] = or3;  g_zo[ob + 5600] = oi3;
    }
}

// ---------------- inverse DFT along H: complex-packed ----------------
__global__ void __launch_bounds__(320) k_invH() {
    __shared__ __align__(16) float2 zsA[800];
    __shared__ __align__(16) float2 zsB[800];
    int tid = threadIdx.x;
    int bo = blockIdx.x;
    for (int i = tid; i < 800; i += 320) {
        float zr = g_zo[(size_t)bo * 1600 + i];
        float zi = g_zo[(size_t)bo * 1600 + 800 + i];
        zsA[i] = make_float2(zr, zi);
        zsB[i] = make_float2(-zi, zr);
    }
    __syncthreads();
#pragma unroll
    for (int v = tid; v < 640; v += 320) {
        int h0 = v / 10, kyp = v - (v / 10) * 10;
        int h1 = h0 + 64, kyg = kyp * 2;
        u64 U00 = pk(0.f, 0.f), U01 = U00, U10 = U00, U11 = U00;
#pragma unroll 4
        for (int kx = 0; kx < 40; kx++) {
            float2 cs0 = __ldg(&g_ThP[kx * 128 + h0]);
            float2 cs1 = __ldg(&g_ThP[kx * 128 + h1]);
            u64 c0 = pk2(cs0.x), s0 = pk2(cs0.y);
            u64 c1 = pk2(cs1.x), s1 = pk2(cs1.y);
            ulonglong2 za = *(const ulonglong2*)&zsA[kx * 20 + kyg];
            ulonglong2 zb = *(const ulonglong2*)&zsB[kx * 20 + kyg];
            fma2(U00, za.x, c0); fma2(U00, zb.x, s0);
            fma2(U01, za.y, c0); fma2(U01, zb.y, s0);
            fma2(U10, za.x, c1); fma2(U10, zb.x, s1);
            fma2(U11, za.y, c1); fma2(U11, zb.y, s1);
        }
        float ur, ui;
        size_t ub = (size_t)bo * 5120;
        unpk(U00, ur, ui); g_y1[ub + h0 * 40 + kyg]     = ur; g_y1[ub + h0 * 40 + 20 + kyg]     = ui;
        unpk(U01, ur, ui); g_y1[ub + h0 * 40 + kyg + 1] = ur; g_y1[ub + h0 * 40 + 20 + kyg + 1] = ui;
        unpk(U10, ur, ui); g_y1[ub + h1 * 40 + kyg]     = ur; g_y1[ub + h1 * 40 + 20 + kyg]     = ui;
        unpk(U11, ur, ui); g_y1[ub + h1 * 40 + kyg + 1] = ur; g_y1[ub + h1 * 40 + 20 + kyg + 1] = ui;
    }
}

// ---------------- inverse rfft along W via tf32 MMA (3-term split) ----------------
__global__ void __launch_bounds__(256) k_invW_mma() {
    __shared__ float us_hi[40 * 133], us_lo[40 * 133];
    int tid = threadIdx.x;
    int lane = tid & 31, warp = tid >> 5;
    int tig = lane & 3, gid = lane >> 2;
    int bo = blockIdx.x;
    const float* ub = g_y1 + (size_t)bo * 5120;
    for (int i = tid; i < 5120; i += 256) {
        int h = i / 40, k = i - h * 40;
        float v = ub[i];
        uint32_t hb = f2tf32(v);
        float hv = __uint_as_float(hb);
        us_hi[k * 133 + h] = hv;
        us_lo[k * 133 + h] = __uint_as_float(f2tf32(v - hv));
    }
    __syncthreads();
    float acc[16][4];
#pragma unroll
    for (int nf = 0; nf < 16; nf++)
#pragma unroll
        for (int r = 0; r < 4; r++) acc[nf][r] = 0.f;
#pragma unroll
    for (int k8 = 0; k8 < 5; k8++) {
        int k = k8 * 8 + tig;
        const uint32_t* ah = (const uint32_t*)&us_hi[k * 133 + warp * 16 + gid];
        const uint32_t* al = (const uint32_t*)&us_lo[k * 133 + warp * 16 + gid];
        uint32_t ah0 = ah[0], ah1 = ah[8], ah2 = ah[4 * 133], ah3 = ah[4 * 133 + 8];
        uint32_t al0 = al[0], al1 = al[8], al2 = al[4 * 133], al3 = al[4 * 133 + 8];
#pragma unroll
        for (int nf = 0; nf < 16; nf++) {
            const uint32_t* bh = (const uint32_t*)&g_Ghi[k * 128 + nf * 8 + gid];
            const uint32_t* bl = (const uint32_t*)&g_Glo[k * 128 + nf * 8 + gid];
            uint32_t bh0 = __ldg(bh), bh1 = __ldg(bh + 4 * 128);
            uint32_t bl0 = __ldg(bl), bl1 = __ldg(bl + 4 * 128);
            MMA_TF32(acc[nf][0], acc[nf][1], acc[nf][2], acc[nf][3],
                     ah0, ah1, ah2, ah3, bh0, bh1);
            MMA_TF32(acc[nf][0], acc[nf][1], acc[nf][2], acc[nf][3],
                     al0, al1, al2, al3, bh0, bh1);
            MMA_TF32(acc[nf][0], acc[nf][1], acc[nf][2], acc[nf][3],
                     ah0, ah1, ah2, ah3, bl0, bl1);
        }
    }
    float* xo = g_x1 + (size_t)bo * NPIX;
    int h = warp * 16 + gid;
#pragma unroll
    for (int nf = 0; nf < 16; nf++) {
        int n = nf * 8 + 2 * tig;
        *(float2*)&xo[(size_t)h * 128 + n]       = make_float2(acc[nf][0], acc[nf][1]);
        *(float2*)&xo[(size_t)(h + 8) * 128 + n] = make_float2(acc[nf][2], acc[nf][3]);
    }
}

// ---------------- conv3x3 via tf32 tensor cores ----------------
#define CONV_TS_ELEMS (16 * 524)
#define CONV_WS_ELEMS (144 * 66)
#define CONV_SMEM_BYTES ((CONV_TS_ELEMS + CONV_WS_ELEMS) * 4)

__global__ void __launch_bounds__(256) k_conv_mma(const float* __restrict__ cb, int layer)
{
    extern __shared__ float sm[];
    float* ts = sm;
    float* wsh = sm + CONV_TS_ELEMS;
    int tid = threadIdx.x;
    int lane = tid & 31, warp = tid >> 5;
    int warpM = warp & 3, warpN = warp >> 2;
    int tig = lane & 3, gid = lane >> 2;
    int b = blockIdx.y;
    int h0 = blockIdx.x * 2;
    const float* xin = g_x + (size_t)b * 64 * NPIX;
    const float* cwT = g_cwT + (size_t)layer * 9 * 4096;

    float acc[4][4][4];
#pragma unroll
    for (int nf = 0; nf < 4; nf++) {
        int o = warpN * 32 + nf * 8 + 2 * tig;
        float bb0 = __ldg(&cb[layer * 64 + o]);
        float bb1 = __ldg(&cb[layer * 64 + o + 1]);
#pragma unroll
        for (int mf = 0; mf < 4; mf++) {
            acc[mf][nf][0] = bb0; acc[mf][nf][1] = bb1;
            acc[mf][nf][2] = bb0; acc[mf][nf][3] = bb1;
        }
    }

    for (int chunk = 0; chunk < 4; chunk++) {
        int c0 = chunk * 16;
        __syncthreads();
        for (int i = tid; i < 16 * 4 * 131; i += 256) {
            int cc = i / 524; int rem = i - cc * 524;
            int rr = rem / 131; int ww = rem - rr * 131;
            int gh = (h0 + rr - 1) & 127;
            int gw = (ww - 1) & 127;
            float v = xin[(size_t)(c0 + cc) * NPIX + gh * 128 + gw];
            ts[i] = __uint_as_float(f2tf32(v));
        }
        for (int i = tid; i < 9216; i += 256) {
            int t9 = i >> 10; int rem = i & 1023;
            int kg = rem >> 6; int o = rem & 63;
            wsh[(t9 * 16 + kg) * 66 + o] = cwT[(size_t)t9 * 4096 + (c0 + kg) * 64 + o];
        }
        __syncthreads();
#pragma unroll
        for (int tap = 0; tap < 9; tap++) {
            int dy = tap / 3, dx = tap - 3 * dy;
#pragma unroll
            for (int k8 = 0; k8 < 2; k8++) {
                uint32_t bfr[4][2];
                const uint32_t* wp = (const uint32_t*)&wsh[(tap * 16 + k8 * 8 + tig) * 66 + warpN * 32 + gid];
#pragma unroll
                for (int nf = 0; nf < 4; nf++) {
                    bfr[nf][0] = wp[nf * 8];
                    bfr[nf][1] = wp[nf * 8 + 4 * 66];
                }
#pragma unroll
                for (int mf = 0; mf < 4; mf++) {
                    int pbase = warpM * 64 + mf * 16;
                    int row = (pbase >> 7) + dy;
                    int wb = (pbase & 127) + gid + dx;
                    const uint32_t* ap = (const uint32_t*)&ts[(k8 * 8 + tig) * 524 + row * 131 + wb];
                    uint32_t a0 = ap[0], a1 = ap[8], a2 = ap[4 * 524], a3 = ap[4 * 524 + 8];
#pragma unroll
                    for (int nf = 0; nf < 4; nf++) {
                        MMA_TF32(acc[mf][nf][0], acc[mf][nf][1], acc[mf][nf][2], acc[mf][nf][3],
                                 a0, a1, a2, a3, bfr[nf][0], bfr[nf][1]);
                    }
                }
            }
        }
    }
    size_t obase = ((size_t)b * 64) * NPIX + (size_t)h0 * 128;
#pragma unroll
    for (int mf = 0; mf < 4; mf++) {
        int p_lo = warpM * 64 + mf * 16 + gid;
#pragma unroll
        for (int nf = 0; nf < 4; nf++) {
            int o = warpN * 32 + nf * 8 + 2 * tig;
            float* dst = g_x2 + obase + (size_t)o * NPIX;
            dst[p_lo]            = acc[mf][nf][0];
            dst[NPIX + p_lo]     = acc[mf][nf][1];
            dst[p_lo + 8]        = acc[mf][nf][2];
            dst[NPIX + p_lo + 8] = acc[mf][nf][3];
        }
    }
}

// ---------------- products + pointwise mix + fast-exact tanh residual (FFMA2) ----------------
__global__ void __launch_bounds__(256) k_combine(
    const float* __restrict__ pw, const float* __restrict__ pb, int layer)
{
    __shared__ __align__(16) float wst[130 * 68];
    __shared__ float bs[64];
    int tid = threadIdx.x;
    for (int i = tid; i < 8320; i += 256) {
        int o = i / 130, c = i - o * 130;
        wst[c * 68 + o] = pw[(size_t)layer * 8320 + i];
    }
    if (tid < 64) bs[tid] = pb[layer * 64 + tid];
    __syncthreads();
    int po = tid & 127, oh = tid >> 7, ob = oh * 32;
    int p0 = blockIdx.x * 256 + po;
    int b = p0 >> 14, pix0 = p0 & 16383;
    const float* x1p = g_x1 + ((size_t)b * 64) * NPIX + pix0;
    const float* x2p = g_x2 + ((size_t)b * 64) * NPIX + pix0;
    u64 acc0[16], acc1[16];
#pragma unroll
    for (int q = 0; q < 16; q++) {
        u64 v = pk(bs[ob + 2 * q], bs[ob + 2 * q + 1]);
        acc0[q] = v; acc1[q] = v;
    }
#pragma unroll 4
    for (int c = 0; c < 64; c++) {
        u64 A0 = pk2(x1p[(size_t)c * NPIX]);
        u64 A1 = pk2(x1p[(size_t)c * NPIX + 128]);
        u64 D0 = pk2(x2p[(size_t)c * NPIX]);
        u64 D1 = pk2(x2p[(size_t)c * NPIX + 128]);
        const float* wa = &wst[c * 68 + ob];
        const float* wd = &wst[(64 + c) * 68 + ob];
#pragma unroll
        for (int q8 = 0; q8 < 8; q8++) {
            ulonglong2 wva = *(const ulonglong2*)&wa[q8 * 4];
            fma2(acc0[q8 * 2],     wva.x, A0); fma2(acc0[q8 * 2 + 1], wva.y, A0);
            fma2(acc1[q8 * 2],     wva.x, A1); fma2(acc1[q8 * 2 + 1], wva.y, A1);
            ulonglong2 wvd = *(const ulonglong2*)&wd[q8 * 4];
            fma2(acc0[q8 * 2],     wvd.x, D0); fma2(acc0[q8 * 2 + 1], wvd.y, D0);
            fma2(acc1[q8 * 2],     wvd.x, D1); fma2(acc1[q8 * 2 + 1], wvd.y, D1);
        }
    }
    float p00 = x1p[0] * x1p[(size_t)2 * NPIX];
    float p01 = x1p[(size_t)1 * NPIX] * x1p[(size_t)3 * NPIX];
    float p10 = x1p[128] * x1p[(size_t)2 * NPIX + 128];
    float p11 = x1p[(size_t)1 * NPIX + 128] * x1p[(size_t)3 * NPIX + 128];
    {
        u64 P00 = pk2(p00), P01 = pk2(p01), P10 = pk2(p10), P11 = pk2(p11);
        const float* w0r = &wst[128 * 68 + ob];
        const float* w1r = &wst[129 * 68 + ob];
#pragma unroll
        for (int q8 = 0; q8 < 8; q8++) {
            ulonglong2 w0v = *(const ulonglong2*)&w0r[q8 * 4];
            ulonglong2 w1v = *(const ulonglong2*)&w1r[q8 * 4];
            fma2(acc0[q8 * 2],     w0v.x, P00); fma2(acc0[q8 * 2 + 1], w0v.y, P00);
            fma2(acc0[q8 * 2],     w1v.x, P01); fma2(acc0[q8 * 2 + 1], w1v.y, P01);
            fma2(acc1[q8 * 2],     w0v.x, P10); fma2(acc1[q8 * 2 + 1], w0v.y, P10);
            fma2(acc1[q8 * 2],     w1v.x, P11); fma2(acc1[q8 * 2 + 1], w1v.y, P11);
        }
    }
    float* xp = g_x + ((size_t)b * 64 + ob) * NPIX + pix0;
#pragma unroll
    for (int q = 0; q < 16; q++) {
        float lo, hi;
        unpk(acc0[q], lo, hi);
        xp[(size_t)(2 * q) * NPIX]           += tanh_e(lo);
        xp[(size_t)(2 * q + 1) * NPIX]       += tanh_e(hi);
        unpk(acc1[q], lo, hi);
        xp[(size_t)(2 * q) * NPIX + 128]     += tanh_e(lo);
        xp[(size_t)(2 * q + 1) * NPIX + 128] += tanh_e(hi);
    }
}

// ---------------- final projection MLP ----------------
__global__ void __launch_bounds__(128) k_final(
    const float* __restrict__ w1, const float* __restrict__ b1,
    const float* __restrict__ w2, const float* __restrict__ b2,
    float* __restrict__ out)
{
    __shared__ __align__(16) float w1s[128 * 64];
    __shared__ float b1s[128], w2s[128];
    int tid = threadIdx.x;
    for (int i = tid; i < 8192; i += 128) w1s[i] = w1[i];
    b1s[tid] = b1[tid];
    w2s[tid] = w2[tid];
    __syncthreads();
    int p = blockIdx.x * 128 + tid;
    int b = p >> 14, pix = p & 16383;
    const float* xp = g_x + ((size_t)b * 64) * NPIX + pix;
    u64 xv2[32];
#pragma unroll
    for (int c = 0; c < 32; c++)
        xv2[c] = pk(xp[(size_t)(2 * c) * NPIX], xp[(size_t)(2 * c + 1) * NPIX]);
    float acc = b2[0];
    for (int m = 0; m < 128; m++) {
        u64 a0 = pk(0.f, 0.f), a1 = a0, a2 = a0, a3 = a0;
        const float* wr = &w1s[m * 64];
#pragma unroll
        for (int q = 0; q < 16; q++) {
            ulonglong2 wv = *(const ulonglong2*)&wr[q * 4];
            if ((q & 1) == 0) { fma2(a0, wv.x, xv2[q * 2]); fma2(a1, wv.y, xv2[q * 2 + 1]); }
            else              { fma2(a2, wv.x, xv2[q * 2]); fma2(a3, wv.y, xv2[q * 2 + 1]); }
        }
        float l0, h0, l1, h1, l2, h2, l3, h3;
        unpk(a0, l0, h0); unpk(a1, l1, h1); unpk(a2, l2, h2); unpk(a3, l3, h3);
        float t = b1s[m] + ((l0 + h0) + (l1 + h1)) + ((l2 + h2) + (l3 + h3));
        acc += w2s[m] * gelu_t(t);
    }
    out[p] = acc;
}

// ---------------- launch ----------------
extern "C" void kernel_launch(void* const* d_in, const int* in_sizes, int n_in,
                              void* d_out, int out_size)
{
    const float* x      = (const float*)d_in[0];
    const float* qa     = (const float*)d_in[1];
    const float* qb     = (const float*)d_in[2];
    const float* fc0_w1 = (const float*)d_in[3];
    const float* fc0_b1 = (const float*)d_in[4];
    const float* fc0_w2 = (const float*)d_in[5];
    const float* fc0_b2 = (const float*)d_in[6];
    const float* sw1r   = (const float*)d_in[7];
    const float* sw1i   = (const float*)d_in[8];
    const float* sw2r   = (const float*)d_in[9];
    const float* sw2i   = (const float*)d_in[10];
    const float* cw     = (const float*)d_in[11];
    const float* cb     = (const float*)d_in[12];
    const float* pw     = (const float*)d_in[13];
    const float* pb     = (const float*)d_in[14];
    const float* fc1_w1 = (const float*)d_in[15];
    const float* fc1_b1 = (const float*)d_in[16];
    const float* fc1_w2 = (const float*)d_in[17];
    const float* fc1_b2 = (const float*)d_in[18];
    float* out = (float*)d_out;

    static int smem_set = 0;
    if (!smem_set) {
        cudaFuncSetAttribute(k_conv_mma, cudaFuncAttributeMaxDynamicSharedMemorySize, CONV_SMEM_BYTES);
        smem_set = 1;
    }

    k_init_tables<<<20, 256>>>();
    k_wt<<<dim3(13, 128, 16), dim3(32, 8)>>>(sw1r, sw1i, sw2r, sw2i);
    k_cwt<<<(147456 + 255) / 256, 256>>>(cw);
    k_lift<<<2048, 128>>>(x, qa, qb, fc0_w1, fc0_b1, fc0_w2, fc0_b2);

    for (int layer = 0; layer < 4; layer++) {
        k_fwdW_mma<<<2048, 256>>>();
        k_fwdH<<<2048, 256>>>();
        k_mix<<<800, 256>>>(layer);
        k_invH<<<2048, 320>>>();
        k_invW_mma<<<2048, 256>>>();
        k_conv_mma<<<dim3(64, 32), 256, CONV_SMEM_BYTES>>>(cb, layer);
        k_combine<<<2048, 256>>>(pw, pb, layer);
    }

    k_final<<<4096, 128>>>(fc1_w1, fc1_b1, fc1_w2, fc1_b2, out);
}

// round 13
// speedup vs baseline: 1.0987x; 1.0987x over previous
#include <cuda_runtime.h>
#include <cstdint>

#define BB 32
#define NPIX 16384
#define WIDTH 64

typedef unsigned long long u64;

__device__ __forceinline__ u64 pk(float lo, float hi) {
    u64 r; asm("mov.b64 %0, {%1, %2};" : "=l"(r) : "f"(lo), "f"(hi)); return r;
}
__device__ __forceinline__ u64 pk2(float v) {
    u64 r; asm("mov.b64 %0, {%1, %1};" : "=l"(r) : "f"(v)); return r;
}
__device__ __forceinline__ void fma2(u64& d, u64 a, u64 b) {
    asm("fma.rn.f32x2 %0, %1, %2, %0;" : "+l"(d) : "l"(a), "l"(b));
}
__device__ __forceinline__ void unpk(u64 v, float& lo, float& hi) {
    asm("mov.b64 {%0, %1}, %2;" : "=f"(lo), "=f"(hi) : "l"(v));
}
__device__ __forceinline__ uint32_t f2tf32(float v) {
    uint32_t r; asm("cvt.rna.tf32.f32 %0, %1;" : "=r"(r) : "f"(v)); return r;
}
__device__ __forceinline__ float tanh_fast(float x) {
    float r; asm("tanh.approx.f32 %0, %1;" : "=f"(r) : "f"(x)); return r;
}
#define MMA_TF32(c0,c1,c2,c3,a0,a1,a2,a3,b0,b1) \
    asm volatile("mma.sync.aligned.m16n8k8.row.col.f32.tf32.tf32.f32 " \
        "{%0,%1,%2,%3}, {%4,%5,%6,%7}, {%8,%9}, {%0,%1,%2,%3};" \
        : "+f"(c0), "+f"(c1), "+f"(c2), "+f"(c3) \
        : "r"(a0), "r"(a1), "r"(a2), "r"(a3), "r"(b0), "r"(b1))

// ---------------- scratch ----------------
__device__ float g_x [ (size_t)BB*WIDTH*NPIX ];
__device__ float g_x1[ (size_t)BB*WIDTH*NPIX ];
__device__ float g_x2[ (size_t)BB*WIDTH*NPIX ];
__device__ float g_y1[ (size_t)BB*WIDTH*5120 ];
__device__ float g_z [ (size_t)BB*WIDTH*1600 ];
__device__ float g_zo[ (size_t)BB*WIDTH*1600 ];
__device__ float g_Tf  [40*128];
__device__ float g_TfT [128*40];
__device__ float2 g_ThP[40*128];
__device__ float g_TfThi[128*40], g_TfTlo[128*40];
__device__ float g_Ghi[40*128],  g_Glo[40*128];
__device__ float g_wT[(size_t)4*2*2*400*4096];
__device__ float g_cwT[4*9*64*64];

__device__ __forceinline__ float gelu_t(float x) {
    float x3 = x * x * x;
    return 0.5f * x * (1.0f + tanh_fast(0.7978845608028654f * (x + 0.044715f * x3)));
}

__global__ void k_init_tables() {
    for (int i = threadIdx.x + blockIdx.x * blockDim.x; i < 40 * 128; i += blockDim.x * gridDim.x) {
        int k = i / 128, w = i % 128;
        float s, c, tf;
        if (k < 20) { sincospif((float)((w * k) & 127) / 64.0f, &s, &c); tf = c; }
        else        { sincospif((float)((w * (k - 20)) & 127) / 64.0f, &s, &c); tf = -s; }
        g_Tf[i] = tf;
        g_TfT[w * 40 + k] = tf;
        uint32_t hb = f2tf32(tf);
        float hv = __uint_as_float(hb);
        g_TfThi[w * 40 + k] = hv;
        g_TfTlo[w * 40 + k] = __uint_as_float(f2tf32(tf - hv));
        int kxv = (k < 20) ? k : (108 + (k - 20));
        sincospif((float)((w * kxv) & 127) / 64.0f, &s, &c);
        g_ThP[i] = make_float2(c, s);
        const float inv = 1.0f / 16384.0f;
        float gv;
        if (k == 0)       gv = inv;
        else if (k < 20)  { sincospif((float)((w * k) & 127) / 64.0f, &s, &c); gv = 2.0f * inv * c; }
        else if (k == 20) gv = 0.0f;
        else              { sincospif((float)((w * (k - 20)) & 127) / 64.0f, &s, &c); gv = -2.0f * inv * s; }
        uint32_t gb = f2tf32(gv);
        float gh = __uint_as_float(gb);
        g_Ghi[k * 128 + w] = gh;
        g_Glo[k * 128 + w] = __uint_as_float(f2tf32(gv - gh));
    }
}

// ---------------- one-time spectral weight transpose ----------------
__global__ void k_wt(const float* __restrict__ sw1r, const float* __restrict__ sw1i,
                     const float* __restrict__ sw2r, const float* __restrict__ sw2i)
{
    __shared__ float t[32][33];
    int lqc = blockIdx.z;
    int l = lqc >> 2, q = (lqc >> 1) & 1, c = lqc & 1;
    const float* src = (c == 0) ? (q ? sw2r : sw1r) : (q ? sw2i : sw1i);
    src += (size_t)l * 1638400;
    int c0 = blockIdx.x * 32, r0 = blockIdx.y * 32;
    for (int j = threadIdx.y; j < 32; j += 8) {
        int col = c0 + threadIdx.x;
        if (col < 400) t[j][threadIdx.x] = src[(size_t)(r0 + j) * 400 + col];
    }
    __syncthreads();
    float* dst = g_wT + (size_t)lqc * 400 * 4096;
    for (int j = threadIdx.y; j < 32; j += 8) {
        int col = c0 + j;
        if (col < 400) dst[(size_t)col * 4096 + r0 + threadIdx.x] = t[threadIdx.x][j];
    }
}

// ---------------- one-time conv weight transpose + tf32 round ----------------
__global__ void k_cwt(const float* __restrict__ cw) {
    int i = blockIdx.x * 256 + threadIdx.x;
    if (i >= 4 * 9 * 64 * 64) return;
    int o = i & 63; int rem = i >> 6;
    int c = rem & 63; rem >>= 6;
    int tap = rem % 9; int l = rem / 9;
    float v = cw[(((size_t)l * 64 + o) * 64 + c) * 9 + tap];
    g_cwT[((size_t)(l * 9 + tap) * 64 + c) * 64 + o] = __uint_as_float(f2tf32(v));
}

// ---------------- lift: 2 pixels/thread ----------------
__global__ void __launch_bounds__(128) k_lift(
    const float* __restrict__ xin, const float* __restrict__ qa, const float* __restrict__ qb,
    const float* __restrict__ w1, const float* __restrict__ b1,
    const float* __restrict__ w2, const float* __restrict__ b2)
{
    __shared__ float qas[48], qbs[48], b2s[48];
    __shared__ __align__(16) float w1s[128 * 16];
    __shared__ float b1s[128];
    __shared__ __align__(16) float w2t[128 * 48];
    int tid = threadIdx.x;
    if (tid < 48) { qas[tid] = qa[tid]; qbs[tid] = qb[tid]; b2s[tid] = b2[tid]; }
    b1s[tid] = b1[tid];
    for (int i = tid; i < 2048; i += 128) w1s[i] = w1[i];
    for (int i = tid; i < 6144; i += 128) { int o = i / 128, m = i % 128; w2t[m * 48 + o] = w2[i]; }
    __syncthreads();
    int p0 = blockIdx.x * 256 + tid;
    int b = p0 >> 14, pix0 = p0 & 16383;
    int h0 = pix0 >> 7, w0 = pix0 & 127;
    int h1 = h0 + 1;
    float f0[16], f1[16];
    const float* xp = xin + ((size_t)b * 10) * NPIX + pix0;
#pragma unroll
    for (int c = 0; c < 10; c++) { f0[c] = xp[(size_t)c * NPIX]; f1[c] = xp[(size_t)c * NPIX + 128]; }
    f0[10] = (float)h0 * (1.0f / 127.0f);  f1[10] = (float)h1 * (1.0f / 127.0f);
    f0[11] = (float)w0 * (1.0f / 127.0f);  f1[11] = f0[11];
#pragma unroll
    for (int j = 0; j < 4; j++) {
        float sa0 = 0.f, sb0 = 0.f, sa1 = 0.f, sb1 = 0.f;
#pragma unroll
        for (int c = 0; c < 12; c++) {
            float wa = qas[j * 12 + c], wb = qbs[j * 12 + c];
            sa0 += wa * f0[c]; sb0 += wb * f0[c];
            sa1 += wa * f1[c]; sb1 += wb * f1[c];
        }
        f0[12 + j] = sa0 * sb0;
        f1[12 + j] = sa1 * sb1;
    }
    u64 acc0[24], acc1[24];
#pragma unroll
    for (int q = 0; q < 24; q++) {
        u64 v = pk(b2s[2 * q], b2s[2 * q + 1]);
        acc0[q] = v; acc1[q] = v;
    }
    for (int m = 0; m < 128; m++) {
        float t0 = b1s[m], t1 = t0;
#pragma unroll
        for (int c = 0; c < 16; c++) {
            float wv = w1s[m * 16 + c];
            t0 += wv * f0[c];
            t1 += wv * f1[c];
        }
        u64 g20 = pk2(gelu_t(t0));
        u64 g21 = pk2(gelu_t(t1));
        const float* wr = &w2t[m * 48];
#pragma unroll
        for (int q4 = 0; q4 < 12; q4++) {
            ulonglong2 wv = *(const ulonglong2*)&wr[q4 * 4];
            fma2(acc0[q4 * 2],     wv.x, g20); fma2(acc0[q4 * 2 + 1], wv.y, g20);
            fma2(acc1[q4 * 2],     wv.x, g21); fma2(acc1[q4 * 2 + 1], wv.y, g21);
        }
    }
    float* op = g_x + ((size_t)b * WIDTH) * NPIX + pix0;
#pragma unroll
    for (int c = 0; c < 16; c++) {
        op[(size_t)c * NPIX]       = f0[c];
        op[(size_t)c * NPIX + 128] = f1[c];
    }
#pragma unroll
    for (int q = 0; q < 24; q++) {
        float lo, hi;
        unpk(acc0[q], lo, hi);
        op[(size_t)(16 + 2 * q) * NPIX] = lo;
        op[(size_t)(17 + 2 * q) * NPIX] = hi;
        unpk(acc1[q], lo, hi);
        op[(size_t)(16 + 2 * q) * NPIX + 128] = lo;
        op[(size_t)(17 + 2 * q) * NPIX + 128] = hi;
    }
}

// ---------------- fwd rfft along W via tf32 MMA (3-term split) ----------------
__global__ void __launch_bounds__(256) k_fwdW_mma() {
    __shared__ float xs_hi[32 * 133], xs_lo[32 * 133];
    int tid = threadIdx.x;
    int lane = tid & 31, warp = tid >> 5;
    int tig = lane & 3, gid = lane >> 2;
    size_t pbase = (size_t)blockIdx.x * 128 * 128;
    float acc[5][4];
#pragma unroll
    for (int nf = 0; nf < 5; nf++)
#pragma unroll
        for (int r = 0; r < 4; r++) acc[nf][r] = 0.f;

    for (int wc = 0; wc < 4; wc++) {
        __syncthreads();
        for (int i = tid; i < 4096; i += 256) {
            int row = i >> 5, wl = i & 31;
            float v = g_x[pbase + (size_t)row * 128 + wc * 32 + wl];
            uint32_t hb = f2tf32(v);
            float hv = __uint_as_float(hb);
            xs_hi[wl * 133 + row] = hv;
            xs_lo[wl * 133 + row] = __uint_as_float(f2tf32(v - hv));
        }
        __syncthreads();
#pragma unroll
        for (int k8 = 0; k8 < 4; k8++) {
            const uint32_t* ah = (const uint32_t*)&xs_hi[(k8 * 8 + tig) * 133 + warp * 16 + gid];
            const uint32_t* al = (const uint32_t*)&xs_lo[(k8 * 8 + tig) * 133 + warp * 16 + gid];
            uint32_t ah0 = ah[0], ah1 = ah[8], ah2 = ah[4 * 133], ah3 = ah[4 * 133 + 8];
            uint32_t al0 = al[0], al1 = al[8], al2 = al[4 * 133], al3 = al[4 * 133 + 8];
            int kglob = wc * 32 + k8 * 8 + tig;
#pragma unroll
            for (int nf = 0; nf < 5; nf++) {
                const uint32_t* bh = (const uint32_t*)&g_TfThi[kglob * 40 + nf * 8 + gid];
                const uint32_t* bl = (const uint32_t*)&g_TfTlo[kglob * 40 + nf * 8 + gid];
                uint32_t bh0 = __ldg(bh), bh1 = __ldg(bh + 4 * 40);
                uint32_t bl0 = __ldg(bl), bl1 = __ldg(bl + 4 * 40);
                MMA_TF32(acc[nf][0], acc[nf][1], acc[nf][2], acc[nf][3],
                         ah0, ah1, ah2, ah3, bh0, bh1);
                MMA_TF32(acc[nf][0], acc[nf][1], acc[nf][2], acc[nf][3],
                         al0, al1, al2, al3, bh0, bh1);
                MMA_TF32(acc[nf][0], acc[nf][1], acc[nf][2], acc[nf][3],
                         ah0, ah1, ah2, ah3, bl0, bl1);
            }
        }
    }
    size_t row0 = (size_t)blockIdx.x * 128 + warp * 16 + gid;
#pragma unroll
    for (int nf = 0; nf < 5; nf++) {
        int n = nf * 8 + 2 * tig;
        *(float2*)&g_y1[row0 * 40 + n]       = make_float2(acc[nf][0], acc[nf][1]);
        *(float2*)&g_y1[(row0 + 8) * 40 + n] = make_float2(acc[nf][2], acc[nf][3]);
    }
}

// ---------------- fwd DFT along H: complex-packed ----------------
__global__ void __launch_bounds__(256) k_fwdH() {
    __shared__ __align__(16) float2 ysA[2560];
    __shared__ __align__(16) float2 ysB[2560];
    int tid = threadIdx.x;
    int bc = blockIdx.x;
    const float* src = g_y1 + (size_t)bc * 5120;
    for (int i = tid; i < 2560; i += 256) {
        int h = i / 20, ky = i - h * 20;
        float yr = src[h * 40 + ky], yi = src[h * 40 + 20 + ky];
        ysA[i] = make_float2(yr, yi);
        ysB[i] = make_float2(yi, -yr);
    }
    __syncthreads();
    if (tid < 200) {
        int kx0 = tid / 10, kyp = tid - (tid / 10) * 10;
        int kx1 = kx0 + 20, kyg = kyp * 2;
        u64 Z0 = pk(0.f, 0.f), Z1 = Z0, Z2 = Z0, Z3 = Z0;
#pragma unroll 4
        for (int h = 0; h < 128; h++) {
            float2 cs0 = __ldg(&g_ThP[kx0 * 128 + h]);
            float2 cs1 = __ldg(&g_ThP[kx1 * 128 + h]);
            u64 c0 = pk2(cs0.x), s0 = pk2(cs0.y);
            u64 c1 = pk2(cs1.x), s1 = pk2(cs1.y);
            ulonglong2 ya = *(const ulonglong2*)&ysA[h * 20 + kyg];
            ulonglong2 yb = *(const ulonglong2*)&ysB[h * 20 + kyg];
            fma2(Z0, ya.x, c0); fma2(Z0, yb.x, s0);
            fma2(Z1, ya.y, c0); fma2(Z1, yb.y, s0);
            fma2(Z2, ya.x, c1); fma2(Z2, yb.x, s1);
            fma2(Z3, ya.y, c1); fma2(Z3, yb.y, s1);
        }
        float zr, zi;
        size_t zb = (size_t)bc * 1600;
        unpk(Z0, zr, zi); g_z[zb + kx0 * 20 + kyg]     = zr; g_z[zb + 800 + kx0 * 20 + kyg]     = zi;
        unpk(Z1, zr, zi); g_z[zb + kx0 * 20 + kyg + 1] = zr; g_z[zb + 800 + kx0 * 20 + kyg + 1] = zi;
        unpk(Z2, zr, zi); g_z[zb + kx1 * 20 + kyg]     = zr; g_z[zb + 800 + kx1 * 20 + kyg]     = zi;
        unpk(Z3, zr, zi); g_z[zb + kx1 * 20 + kyg + 1] = zr; g_z[zb + 800 + kx1 * 20 + kyg + 1] = zi;
    }
}

// ---------------- per-mode complex channel mixing ----------------
__global__ void __launch_bounds__(256) k_mix(int layer)
{
    __shared__ __align__(16) float Wr[64 * 64], Wi[64 * 64];
    __shared__ float Zr[16 * 64], Zi[16 * 64];
    int tid = threadIdx.x;
    int mode = blockIdx.x;
    int kxi = mode / 20, ky = mode - kxi * 20;
    int q = (kxi < 20) ? 0 : 1;
    int kxm = (kxi < 20) ? kxi : kxi - 20;
    size_t col = (size_t)kxm * 20 + ky;
    const float* wrp = g_wT + (((size_t)(layer * 2 + q) * 2 + 0) * 400 + col) * 4096;
    const float* wip = g_wT + (((size_t)(layer * 2 + q) * 2 + 1) * 400 + col) * 4096;
    for (int i = tid; i < 4096; i += 256) {
        Wr[i] = wrp[i]; Wi[i] = wip[i];
    }
    int og = tid & 15, bb = tid >> 4;
    for (int pass = 0; pass < 2; pass++) {
        int b0 = pass * 16;
        __syncthreads();
        for (int i = tid; i < 1024; i += 256) {
            int lb = i >> 6, c = i & 63;
            size_t zb = ((size_t)(b0 + lb) * 64 + c) * 1600 + mode;
            Zr[i] = g_z[zb]; Zi[i] = g_z[zb + 800];
        }
        __syncthreads();
        float or0=0,or1=0,or2=0,or3=0, oi0=0,oi1=0,oi2=0,oi3=0;
#pragma unroll 8
        for (int i2 = 0; i2 < 64; i2++) {
            float zr = Zr[bb * 64 + i2], zi = Zi[bb * 64 + i2];
            float4 wr4 = *(const float4*)&Wr[i2 * 64 + og * 4];
            float4 wi4 = *(const float4*)&Wi[i2 * 64 + og * 4];
            or0 += zr * wr4.x - zi * wi4.x;  oi0 += zr * wi4.x + zi * wr4.x;
            or1 += zr * wr4.y - zi * wi4.y;  oi1 += zr * wi4.y + zi * wr4.y;
            or2 += zr * wr4.z - zi * wi4.z;  oi2 += zr * wi4.z + zi * wr4.z;
            or3 += zr * wr4.w - zi * wi4.w;  oi3 += zr * wi4.w + zi * wr4.w;
        }
        size_t ob = ((size_t)(b0 + bb) * 64 + og * 4) * 1600 + mode;
        g_zo[ob]        = or0;  g_zo[ob + 800]  = oi0;
        g_zo[ob + 1600] = or1;  g_zo[ob + 2400] = oi1;
        g_zo[ob + 3200] = or2;  g_zo[ob + 4000] = oi2;
        g_zo[ob + 4800] = or3;  g_zo[ob + 5600] = oi3;
    }
}

// ---------------- inverse DFT along H: complex-packed ----------------
__global__ void __launch_bounds__(320) k_invH() {
    __shared__ __align__(16) float2 zsA[800];
    __shared__ __align__(16) float2 zsB[800];
    int tid = threadIdx.x;
    int bo = blockIdx.x;
    for (int i = tid; i < 800; i += 320) {
        float zr = g_zo[(size_t)bo * 1600 + i];
        float zi = g_zo[(size_t)bo * 1600 + 800 + i];
        zsA[i] = make_float2(zr, zi);
        zsB[i] = make_float2(-zi, zr);
    }
    __syncthreads();
#pragma unroll
    for (int v = tid; v < 640; v += 320) {
        int h0 = v / 10, kyp = v - (v / 10) * 10;
        int h1 = h0 + 64, kyg = kyp * 2;
        u64 U00 = pk(0.f, 0.f), U01 = U00, U10 = U00, U11 = U00;
#pragma unroll 4
        for (int kx = 0; kx < 40; kx++) {
            float2 cs0 = __ldg(&g_ThP[kx * 128 + h0]);
            float2 cs1 = __ldg(&g_ThP[kx * 128 + h1]);
            u64 c0 = pk2(cs0.x), s0 = pk2(cs0.y);
            u64 c1 = pk2(cs1.x), s1 = pk2(cs1.y);
            ulonglong2 za = *(const ulonglong2*)&zsA[kx * 20 + kyg];
            ulonglong2 zb = *(const ulonglong2*)&zsB[kx * 20 + kyg];
            fma2(U00, za.x, c0); fma2(U00, zb.x, s0);
            fma2(U01, za.y, c0); fma2(U01, zb.y, s0);
            fma2(U10, za.x, c1); fma2(U10, zb.x, s1);
            fma2(U11, za.y, c1); fma2(U11, zb.y, s1);
        }
        float ur, ui;
        size_t ub = (size_t)bo * 5120;
        unpk(U00, ur, ui); g_y1[ub + h0 * 40 + kyg]     = ur; g_y1[ub + h0 * 40 + 20 + kyg]     = ui;
        unpk(U01, ur, ui); g_y1[ub + h0 * 40 + kyg + 1] = ur; g_y1[ub + h0 * 40 + 20 + kyg + 1] = ui;
        unpk(U10, ur, ui); g_y1[ub + h1 * 40 + kyg]     = ur; g_y1[ub + h1 * 40 + 20 + kyg]     = ui;
        unpk(U11, ur, ui); g_y1[ub + h1 * 40 + kyg + 1] = ur; g_y1[ub + h1 * 40 + 20 + kyg + 1] = ui;
    }
}

// ---------------- inverse rfft along W via tf32 MMA (3-term split) ----------------
__global__ void __launch_bounds__(256) k_invW_mma() {
    __shared__ float us_hi[40 * 133], us_lo[40 * 133];
    int tid = threadIdx.x;
    int lane = tid & 31, warp = tid >> 5;
    int tig = lane & 3, gid = lane >> 2;
    int bo = blockIdx.x;
    const float* ub = g_y1 + (size_t)bo * 5120;
    for (int i = tid; i < 5120; i += 256) {
        int h = i / 40, k = i - h * 40;
        float v = ub[i];
        uint32_t hb = f2tf32(v);
        float hv = __uint_as_float(hb);
        us_hi[k * 133 + h] = hv;
        us_lo[k * 133 + h] = __uint_as_float(f2tf32(v - hv));
    }
    __syncthreads();
    float acc[16][4];
#pragma unroll
    for (int nf = 0; nf < 16; nf++)
#pragma unroll
        for (int r = 0; r < 4; r++) acc[nf][r] = 0.f;
#pragma unroll
    for (int k8 = 0; k8 < 5; k8++) {
        int k = k8 * 8 + tig;
        const uint32_t* ah = (const uint32_t*)&us_hi[k * 133 + warp * 16 + gid];
        const uint32_t* al = (const uint32_t*)&us_lo[k * 133 + warp * 16 + gid];
        uint32_t ah0 = ah[0], ah1 = ah[8], ah2 = ah[4 * 133], ah3 = ah[4 * 133 + 8];
        uint32_t al0 = al[0], al1 = al[8], al2 = al[4 * 133], al3 = al[4 * 133 + 8];
#pragma unroll
        for (int nf = 0; nf < 16; nf++) {
            const uint32_t* bh = (const uint32_t*)&g_Ghi[k * 128 + nf * 8 + gid];
            const uint32_t* bl = (const uint32_t*)&g_Glo[k * 128 + nf * 8 + gid];
            uint32_t bh0 = __ldg(bh), bh1 = __ldg(bh + 4 * 128);
            uint32_t bl0 = __ldg(bl), bl1 = __ldg(bl + 4 * 128);
            MMA_TF32(acc[nf][0], acc[nf][1], acc[nf][2], acc[nf][3],
                     ah0, ah1, ah2, ah3, bh0, bh1);
            MMA_TF32(acc[nf][0], acc[nf][1], acc[nf][2], acc[nf][3],
                     al0, al1, al2, al3, bh0, bh1);
            MMA_TF32(acc[nf][0], acc[nf][1], acc[nf][2], acc[nf][3],
                     ah0, ah1, ah2, ah3, bl0, bl1);
        }
    }
    float* xo = g_x1 + (size_t)bo * NPIX;
    int h = warp * 16 + gid;
#pragma unroll
    for (int nf = 0; nf < 16; nf++) {
        int n = nf * 8 + 2 * tig;
        *(float2*)&xo[(size_t)h * 128 + n]       = make_float2(acc[nf][0], acc[nf][1]);
        *(float2*)&xo[(size_t)(h + 8) * 128 + n] = make_float2(acc[nf][2], acc[nf][3]);
    }
}

// ---------------- conv3x3 via tf32 tensor cores ----------------
#define CONV_TS_ELEMS (16 * 524)
#define CONV_WS_ELEMS (144 * 66)
#define CONV_SMEM_BYTES ((CONV_TS_ELEMS + CONV_WS_ELEMS) * 4)

__global__ void __launch_bounds__(256) k_conv_mma(const float* __restrict__ cb, int layer)
{
    extern __shared__ float sm[];
    float* ts = sm;
    float* wsh = sm + CONV_TS_ELEMS;
    int tid = threadIdx.x;
    int lane = tid & 31, warp = tid >> 5;
    int warpM = warp & 3, warpN = warp >> 2;
    int tig = lane & 3, gid = lane >> 2;
    int b = blockIdx.y;
    int h0 = blockIdx.x * 2;
    const float* xin = g_x + (size_t)b * 64 * NPIX;
    const float* cwT = g_cwT + (size_t)layer * 9 * 4096;

    float acc[4][4][4];
#pragma unroll
    for (int nf = 0; nf < 4; nf++) {
        int o = warpN * 32 + nf * 8 + 2 * tig;
        float bb0 = __ldg(&cb[layer * 64 + o]);
        float bb1 = __ldg(&cb[layer * 64 + o + 1]);
#pragma unroll
        for (int mf = 0; mf < 4; mf++) {
            acc[mf][nf][0] = bb0; acc[mf][nf][1] = bb1;
            acc[mf][nf][2] = bb0; acc[mf][nf][3] = bb1;
        }
    }

    for (int chunk = 0; chunk < 4; chunk++) {
        int c0 = chunk * 16;
        __syncthreads();
        for (int i = tid; i < 16 * 4 * 131; i += 256) {
            int cc = i / 524; int rem = i - cc * 524;
            int rr = rem / 131; int ww = rem - rr * 131;
            int gh = (h0 + rr - 1) & 127;
            int gw = (ww - 1) & 127;
            float v = xin[(size_t)(c0 + cc) * NPIX + gh * 128 + gw];
            ts[i] = __uint_as_float(f2tf32(v));
        }
        for (int i = tid; i < 9216; i += 256) {
            int t9 = i >> 10; int rem = i & 1023;
            int kg = rem >> 6; int o = rem & 63;
            wsh[(t9 * 16 + kg) * 66 + o] = cwT[(size_t)t9 * 4096 + (c0 + kg) * 64 + o];
        }
        __syncthreads();
#pragma unroll
        for (int tap = 0; tap < 9; tap++) {
            int dy = tap / 3, dx = tap - 3 * dy;
#pragma unroll
            for (int k8 = 0; k8 < 2; k8++) {
                uint32_t bfr[4][2];
                const uint32_t* wp = (const uint32_t*)&wsh[(tap * 16 + k8 * 8 + tig) * 66 + warpN * 32 + gid];
#pragma unroll
                for (int nf = 0; nf < 4; nf++) {
                    bfr[nf][0] = wp[nf * 8];
                    bfr[nf][1] = wp[nf * 8 + 4 * 66];
                }
#pragma unroll
                for (int mf = 0; mf < 4; mf++) {
                    int pbase = warpM * 64 + mf * 16;
                    int row = (pbase >> 7) + dy;
                    int wb = (pbase & 127) + gid + dx;
                    const uint32_t* ap = (const uint32_t*)&ts[(k8 * 8 + tig) * 524 + row * 131 + wb];
                    uint32_t a0 = ap[0], a1 = ap[8], a2 = ap[4 * 524], a3 = ap[4 * 524 + 8];
#pragma unroll
                    for (int nf = 0; nf < 4; nf++) {
                        MMA_TF32(acc[mf][nf][0], acc[mf][nf][1], acc[mf][nf][2], acc[mf][nf][3],
                                 a0, a1, a2, a3, bfr[nf][0], bfr[nf][1]);
                    }
                }
            }
        }
    }
    size_t obase = ((size_t)b * 64) * NPIX + (size_t)h0 * 128;
#pragma unroll
    for (int mf = 0; mf < 4; mf++) {
        int p_lo = warpM * 64 + mf * 16 + gid;
#pragma unroll
        for (int nf = 0; nf < 4; nf++) {
            int o = warpN * 32 + nf * 8 + 2 * tig;
            float* dst = g_x2 + obase + (size_t)o * NPIX;
            dst[p_lo]            = acc[mf][nf][0];
            dst[NPIX + p_lo]     = acc[mf][nf][1];
            dst[p_lo + 8]        = acc[mf][nf][2];
            dst[NPIX + p_lo + 8] = acc[mf][nf][3];
        }
    }
}

// ---------------- products + pointwise mix + tanh residual (FFMA2) ----------------
__global__ void __launch_bounds__(256) k_combine(
    const float* __restrict__ pw, const float* __restrict__ pb, int layer)
{
    __shared__ __align__(16) float wst[130 * 68];
    __shared__ float bs[64];
    int tid = threadIdx.x;
    for (int i = tid; i < 8320; i += 256) {
        int o = i / 130, c = i - o * 130;
        wst[c * 68 + o] = pw[(size_t)layer * 8320 + i];
    }
    if (tid < 64) bs[tid] = pb[layer * 64 + tid];
    __syncthreads();
    int po = tid & 127, oh = tid >> 7, ob = oh * 32;
    int p0 = blockIdx.x * 256 + po;
    int b = p0 >> 14, pix0 = p0 & 16383;
    const float* x1p = g_x1 + ((size_t)b * 64) * NPIX + pix0;
    const float* x2p = g_x2 + ((size_t)b * 64) * NPIX + pix0;
    u64 acc0[16], acc1[16];
#pragma unroll
    for (int q = 0; q < 16; q++) {
        u64 v = pk(bs[ob + 2 * q], bs[ob + 2 * q + 1]);
        acc0[q] = v; acc1[q] = v;
    }
#pragma unroll 4
    for (int c = 0; c < 64; c++) {
        u64 A0 = pk2(x1p[(size_t)c * NPIX]);
        u64 A1 = pk2(x1p[(size_t)c * NPIX + 128]);
        u64 D0 = pk2(x2p[(size_t)c * NPIX]);
        u64 D1 = pk2(x2p[(size_t)c * NPIX + 128]);
        const float* wa = &wst[c * 68 + ob];
        const float* wd = &wst[(64 + c) * 68 + ob];
#pragma unroll
        for (int q8 = 0; q8 < 8; q8++) {
            ulonglong2 wva = *(const ulonglong2*)&wa[q8 * 4];
            fma2(acc0[q8 * 2],     wva.x, A0); fma2(acc0[q8 * 2 + 1], wva.y, A0);
            fma2(acc1[q8 * 2],     wva.x, A1); fma2(acc1[q8 * 2 + 1], wva.y, A1);
            ulonglong2 wvd = *(const ulonglong2*)&wd[q8 * 4];
            fma2(acc0[q8 * 2],     wvd.x, D0); fma2(acc0[q8 * 2 + 1], wvd.y, D0);
            fma2(acc1[q8 * 2],     wvd.x, D1); fma2(acc1[q8 * 2 + 1], wvd.y, D1);
        }
    }
    float p00 = x1p[0] * x1p[(size_t)2 * NPIX];
    float p01 = x1p[(size_t)1 * NPIX] * x1p[(size_t)3 * NPIX];
    float p10 = x1p[128] * x1p[(size_t)2 * NPIX + 128];
    float p11 = x1p[(size_t)1 * NPIX + 128] * x1p[(size_t)3 * NPIX + 128];
    {
        u64 P00 = pk2(p00), P01 = pk2(p01), P10 = pk2(p10), P11 = pk2(p11);
        const float* w0r = &wst[128 * 68 + ob];
        const float* w1r = &wst[129 * 68 + ob];
#pragma unroll
        for (int q8 = 0; q8 < 8; q8++) {
            ulonglong2 w0v = *(const ulonglong2*)&w0r[q8 * 4];
            ulonglong2 w1v = *(const ulonglong2*)&w1r[q8 * 4];
            fma2(acc0[q8 * 2],     w0v.x, P00); fma2(acc0[q8 * 2 + 1], w0v.y, P00);
            fma2(acc0[q8 * 2],     w1v.x, P01); fma2(acc0[q8 * 2 + 1], w1v.y, P01);
            fma2(acc1[q8 * 2],     w0v.x, P10); fma2(acc1[q8 * 2 + 1], w0v.y, P10);
            fma2(acc1[q8 * 2],     w1v.x, P11); fma2(acc1[q8 * 2 + 1], w1v.y, P11);
        }
    }
    float* xp = g_x + ((size_t)b * 64 + ob) * NPIX + pix0;
#pragma unroll
    for (int q = 0; q < 16; q++) {
        float lo, hi;
        unpk(acc0[q], lo, hi);
        xp[(size_t)(2 * q) * NPIX]           += tanhf(lo);
        xp[(size_t)(2 * q + 1) * NPIX]       += tanhf(hi);
        unpk(acc1[q], lo, hi);
        xp[(size_t)(2 * q) * NPIX + 128]     += tanhf(lo);
        xp[(size_t)(2 * q + 1) * NPIX + 128] += tanhf(hi);
    }
}

// ---------------- final projection MLP ----------------
__global__ void __launch_bounds__(128) k_final(
    const float* __restrict__ w1, const float* __restrict__ b1,
    const float* __restrict__ w2, const float* __restrict__ b2,
    float* __restrict__ out)
{
    __shared__ __align__(16) float w1s[128 * 64];
    __shared__ float b1s[128], w2s[128];
    int tid = threadIdx.x;
    for (int i = tid; i < 8192; i += 128) w1s[i] = w1[i];
    b1s[tid] = b1[tid];
    w2s[tid] = w2[tid];
    __syncthreads();
    int p = blockIdx.x * 128 + tid;
    int b = p >> 14, pix = p & 16383;
    const float* xp = g_x + ((size_t)b * 64) * NPIX + pix;
    u64 xv2[32];
#pragma unroll
    for (int c = 0; c < 32; c++)
        xv2[c] = pk(xp[(size_t)(2 * c) * NPIX], xp[(size_t)(2 * c + 1) * NPIX]);
    float acc = b2[0];
    for (int m = 0; m < 128; m++) {
        u64 a0 = pk(0.f, 0.f), a1 = a0, a2 = a0, a3 = a0;
        const float* wr = &w1s[m * 64];
#pragma unroll
        for (int q = 0; q < 16; q++) {
            ulonglong2 wv = *(const ulonglong2*)&wr[q * 4];
            if ((q & 1) == 0) { fma2(a0, wv.x, xv2[q * 2]); fma2(a1, wv.y, xv2[q * 2 + 1]); }
            else              { fma2(a2, wv.x, xv2[q * 2]); fma2(a3, wv.y, xv2[q * 2 + 1]); }
        }
        float l0, h0, l1, h1, l2, h2, l3, h3;
        unpk(a0, l0, h0); unpk(a1, l1, h1); unpk(a2, l2, h2); unpk(a3, l3, h3);
        float t = b1s[m] + ((l0 + h0) + (l1 + h1)) + ((l2 + h2) + (l3 + h3));
        acc += w2s[m] * gelu_t(t);
    }
    out[p] = acc;
}

// ---------------- launch ----------------
extern "C" void kernel_launch(void* const* d_in, const int* in_sizes, int n_in,
                              void* d_out, int out_size)
{
    const float* x      = (const float*)d_in[0];
    const float* qa     = (const float*)d_in[1];
    const float* qb     = (const float*)d_in[2];
    const float* fc0_w1 = (const float*)d_in[3];
    const float* fc0_b1 = (const float*)d_in[4];
    const float* fc0_w2 = (const float*)d_in[5];
    const float* fc0_b2 = (const float*)d_in[6];
    const float* sw1r   = (const float*)d_in[7];
    const float* sw1i   = (const float*)d_in[8];
    const float* sw2r   = (const float*)d_in[9];
    const float* sw2i   = (const float*)d_in[10];
    const float* cw     = (const float*)d_in[11];
    const float* cb     = (const float*)d_in[12];
    const float* pw     = (const float*)d_in[13];
    const float* pb     = (const float*)d_in[14];
    const float* fc1_w1 = (const float*)d_in[15];
    const float* fc1_b1 = (const float*)d_in[16];
    const float* fc1_w2 = (const float*)d_in[17];
    const float* fc1_b2 = (const float*)d_in[18];
    float* out = (float*)d_out;

    static cudaStream_t s2 = nullptr;
    static cudaEvent_t evFork = nullptr, evJoin = nullptr;
    if (!s2) {
        cudaFuncSetAttribute(k_conv_mma, cudaFuncAttributeMaxDynamicSharedMemorySize, CONV_SMEM_BYTES);
        cudaStreamCreateWithFlags(&s2, cudaStreamNonBlocking);
        cudaEventCreateWithFlags(&evFork, cudaEventDisableTiming);
        cudaEventCreateWithFlags(&evJoin, cudaEventDisableTiming);
    }

    k_init_tables<<<20, 256>>>();
    k_wt<<<dim3(13, 128, 16), dim3(32, 8)>>>(sw1r, sw1i, sw2r, sw2i);
    k_cwt<<<(147456 + 255) / 256, 256>>>(cw);
    k_lift<<<2048, 128>>>(x, qa, qb, fc0_w1, fc0_b1, fc0_w2, fc0_b2);

    for (int layer = 0; layer < 4; layer++) {
        // fork: conv (stream s2) runs concurrently with the spectral chain (stream 0)
        cudaEventRecord(evFork, 0);
        cudaStreamWaitEvent(s2, evFork, 0);
        k_conv_mma<<<dim3(64, 32), 256, CONV_SMEM_BYTES, s2>>>(cb, layer);
        cudaEventRecord(evJoin, s2);

        k_fwdW_mma<<<2048, 256>>>();
        k_fwdH<<<2048, 256>>>();
        k_mix<<<800, 256>>>(layer);
        k_invH<<<2048, 320>>>();
        k_invW_mma<<<2048, 256>>>();

        cudaStreamWaitEvent(0, evJoin, 0);
        k_combine<<<2048, 256>>>(pw, pb, layer);
    }

    k_final<<<4096, 128>>>(fc1_w1, fc1_b1, fc1_w2, fc1_b2, out);
}

// round 14
// speedup vs baseline: 1.1165x; 1.0162x over previous
#include <cuda_runtime.h>
#include <cstdint>

#define BB 32
#define NPIX 16384
#define WIDTH 64

typedef unsigned long long u64;

__device__ __forceinline__ u64 pk(float lo, float hi) {
    u64 r; asm("mov.b64 %0, {%1, %2};" : "=l"(r) : "f"(lo), "f"(hi)); return r;
}
__device__ __forceinline__ u64 pk2(float v) {
    u64 r; asm("mov.b64 %0, {%1, %1};" : "=l"(r) : "f"(v)); return r;
}
__device__ __forceinline__ void fma2(u64& d, u64 a, u64 b) {
    asm("fma.rn.f32x2 %0, %1, %2, %0;" : "+l"(d) : "l"(a), "l"(b));
}
__device__ __forceinline__ void unpk(u64 v, float& lo, float& hi) {
    asm("mov.b64 {%0, %1}, %2;" : "=f"(lo), "=f"(hi) : "l"(v));
}
__device__ __forceinline__ uint32_t f2tf32(float v) {
    uint32_t r; asm("cvt.rna.tf32.f32 %0, %1;" : "=r"(r) : "f"(v)); return r;
}
__device__ __forceinline__ float tanh_fast(float x) {
    float r; asm("tanh.approx.f32 %0, %1;" : "=f"(r) : "f"(x)); return r;
}
#define MMA_TF32(c0,c1,c2,c3,a0,a1,a2,a3,b0,b1) \
    asm volatile("mma.sync.aligned.m16n8k8.row.col.f32.tf32.tf32.f32 " \
        "{%0,%1,%2,%3}, {%4,%5,%6,%7}, {%8,%9}, {%0,%1,%2,%3};" \
        : "+f"(c0), "+f"(c1), "+f"(c2), "+f"(c3) \
        : "r"(a0), "r"(a1), "r"(a2), "r"(a3), "r"(b0), "r"(b1))

// ---------------- scratch ----------------
__device__ float g_x [ (size_t)BB*WIDTH*NPIX ];
__device__ float g_x1[ (size_t)BB*WIDTH*NPIX ];
__device__ float g_x2[ (size_t)BB*WIDTH*NPIX ];
__device__ float g_y1[ (size_t)BB*WIDTH*5120 ];
__device__ float g_z [ (size_t)BB*WIDTH*1600 ];
__device__ float g_zo[ (size_t)BB*WIDTH*1600 ];
__device__ float g_Tf  [40*128];
__device__ float g_TfT [128*40];
__device__ float2 g_ThP[40*128];
__device__ float g_TfThi[128*40], g_TfTlo[128*40];
__device__ float g_Ghi[40*128],  g_Glo[40*128];
__device__ float g_wT[(size_t)4*2*2*400*4096];
__device__ float g_cwT[4*9*64*64];

__device__ __forceinline__ float gelu_t(float x) {
    float x3 = x * x * x;
    return 0.5f * x * (1.0f + tanh_fast(0.7978845608028654f * (x + 0.044715f * x3)));
}

__global__ void k_init_tables() {
    for (int i = threadIdx.x + blockIdx.x * blockDim.x; i < 40 * 128; i += blockDim.x * gridDim.x) {
        int k = i / 128, w = i % 128;
        float s, c, tf;
        if (k < 20) { sincospif((float)((w * k) & 127) / 64.0f, &s, &c); tf = c; }
        else        { sincospif((float)((w * (k - 20)) & 127) / 64.0f, &s, &c); tf = -s; }
        g_Tf[i] = tf;
        g_TfT[w * 40 + k] = tf;
        uint32_t hb = f2tf32(tf);
        float hv = __uint_as_float(hb);
        g_TfThi[w * 40 + k] = hv;
        g_TfTlo[w * 40 + k] = __uint_as_float(f2tf32(tf - hv));
        int kxv = (k < 20) ? k : (108 + (k - 20));
        sincospif((float)((w * kxv) & 127) / 64.0f, &s, &c);
        g_ThP[i] = make_float2(c, s);
        const float inv = 1.0f / 16384.0f;
        float gv;
        if (k == 0)       gv = inv;
        else if (k < 20)  { sincospif((float)((w * k) & 127) / 64.0f, &s, &c); gv = 2.0f * inv * c; }
        else if (k == 20) gv = 0.0f;
        else              { sincospif((float)((w * (k - 20)) & 127) / 64.0f, &s, &c); gv = -2.0f * inv * s; }
        uint32_t gb = f2tf32(gv);
        float gh = __uint_as_float(gb);
        g_Ghi[k * 128 + w] = gh;
        g_Glo[k * 128 + w] = __uint_as_float(f2tf32(gv - gh));
    }
}

// ---------------- one-time spectral weight transpose ----------------
__global__ void k_wt(const float* __restrict__ sw1r, const float* __restrict__ sw1i,
                     const float* __restrict__ sw2r, const float* __restrict__ sw2i)
{
    __shared__ float t[32][33];
    int lqc = blockIdx.z;
    int l = lqc >> 2, q = (lqc >> 1) & 1, c = lqc & 1;
    const float* src = (c == 0) ? (q ? sw2r : sw1r) : (q ? sw2i : sw1i);
    src += (size_t)l * 1638400;
    int c0 = blockIdx.x * 32, r0 = blockIdx.y * 32;
    for (int j = threadIdx.y; j < 32; j += 8) {
        int col = c0 + threadIdx.x;
        if (col < 400) t[j][threadIdx.x] = src[(size_t)(r0 + j) * 400 + col];
    }
    __syncthreads();
    float* dst = g_wT + (size_t)lqc * 400 * 4096;
    for (int j = threadIdx.y; j < 32; j += 8) {
        int col = c0 + j;
        if (col < 400) dst[(size_t)col * 4096 + r0 + threadIdx.x] = t[threadIdx.x][j];
    }
}

// ---------------- one-time conv weight transpose + tf32 round ----------------
__global__ void k_cwt(const float* __restrict__ cw) {
    int i = blockIdx.x * 256 + threadIdx.x;
    if (i >= 4 * 9 * 64 * 64) return;
    int o = i & 63; int rem = i >> 6;
    int c = rem & 63; rem >>= 6;
    int tap = rem % 9; int l = rem / 9;
    float v = cw[(((size_t)l * 64 + o) * 64 + c) * 9 + tap];
    g_cwT[((size_t)(l * 9 + tap) * 64 + c) * 64 + o] = __uint_as_float(f2tf32(v));
}

// ---------------- lift: 2 pixels/thread ----------------
__global__ void __launch_bounds__(128) k_lift(
    const float* __restrict__ xin, const float* __restrict__ qa, const float* __restrict__ qb,
    const float* __restrict__ w1, const float* __restrict__ b1,
    const float* __restrict__ w2, const float* __restrict__ b2)
{
    __shared__ float qas[48], qbs[48], b2s[48];
    __shared__ __align__(16) float w1s[128 * 16];
    __shared__ float b1s[128];
    __shared__ __align__(16) float w2t[128 * 48];
    int tid = threadIdx.x;
    if (tid < 48) { qas[tid] = qa[tid]; qbs[tid] = qb[tid]; b2s[tid] = b2[tid]; }
    b1s[tid] = b1[tid];
    for (int i = tid; i < 2048; i += 128) w1s[i] = w1[i];
    for (int i = tid; i < 6144; i += 128) { int o = i / 128, m = i % 128; w2t[m * 48 + o] = w2[i]; }
    __syncthreads();
    int p0 = blockIdx.x * 256 + tid;
    int b = p0 >> 14, pix0 = p0 & 16383;
    int h0 = pix0 >> 7, w0 = pix0 & 127;
    int h1 = h0 + 1;
    float f0[16], f1[16];
    const float* xp = xin + ((size_t)b * 10) * NPIX + pix0;
#pragma unroll
    for (int c = 0; c < 10; c++) { f0[c] = xp[(size_t)c * NPIX]; f1[c] = xp[(size_t)c * NPIX + 128]; }
    f0[10] = (float)h0 * (1.0f / 127.0f);  f1[10] = (float)h1 * (1.0f / 127.0f);
    f0[11] = (float)w0 * (1.0f / 127.0f);  f1[11] = f0[11];
#pragma unroll
    for (int j = 0; j < 4; j++) {
        float sa0 = 0.f, sb0 = 0.f, sa1 = 0.f, sb1 = 0.f;
#pragma unroll
        for (int c = 0; c < 12; c++) {
            float wa = qas[j * 12 + c], wb = qbs[j * 12 + c];
            sa0 += wa * f0[c]; sb0 += wb * f0[c];
            sa1 += wa * f1[c]; sb1 += wb * f1[c];
        }
        f0[12 + j] = sa0 * sb0;
        f1[12 + j] = sa1 * sb1;
    }
    u64 acc0[24], acc1[24];
#pragma unroll
    for (int q = 0; q < 24; q++) {
        u64 v = pk(b2s[2 * q], b2s[2 * q + 1]);
        acc0[q] = v; acc1[q] = v;
    }
    for (int m = 0; m < 128; m++) {
        float t0 = b1s[m], t1 = t0;
#pragma unroll
        for (int c = 0; c < 16; c++) {
            float wv = w1s[m * 16 + c];
            t0 += wv * f0[c];
            t1 += wv * f1[c];
        }
        u64 g20 = pk2(gelu_t(t0));
        u64 g21 = pk2(gelu_t(t1));
        const float* wr = &w2t[m * 48];
#pragma unroll
        for (int q4 = 0; q4 < 12; q4++) {
            ulonglong2 wv = *(const ulonglong2*)&wr[q4 * 4];
            fma2(acc0[q4 * 2],     wv.x, g20); fma2(acc0[q4 * 2 + 1], wv.y, g20);
            fma2(acc1[q4 * 2],     wv.x, g21); fma2(acc1[q4 * 2 + 1], wv.y, g21);
        }
    }
    float* op = g_x + ((size_t)b * WIDTH) * NPIX + pix0;
#pragma unroll
    for (int c = 0; c < 16; c++) {
        op[(size_t)c * NPIX]       = f0[c];
        op[(size_t)c * NPIX + 128] = f1[c];
    }
#pragma unroll
    for (int q = 0; q < 24; q++) {
        float lo, hi;
        unpk(acc0[q], lo, hi);
        op[(size_t)(16 + 2 * q) * NPIX] = lo;
        op[(size_t)(17 + 2 * q) * NPIX] = hi;
        unpk(acc1[q], lo, hi);
        op[(size_t)(16 + 2 * q) * NPIX + 128] = lo;
        op[(size_t)(17 + 2 * q) * NPIX + 128] = hi;
    }
}

// ---------------- fwd rfft along W via tf32 MMA (3-term split) ----------------
__global__ void __launch_bounds__(256) k_fwdW_mma() {
    __shared__ float xs_hi[32 * 133], xs_lo[32 * 133];
    int tid = threadIdx.x;
    int lane = tid & 31, warp = tid >> 5;
    int tig = lane & 3, gid = lane >> 2;
    size_t pbase = (size_t)blockIdx.x * 128 * 128;
    float acc[5][4];
#pragma unroll
    for (int nf = 0; nf < 5; nf++)
#pragma unroll
        for (int r = 0; r < 4; r++) acc[nf][r] = 0.f;

    for (int wc = 0; wc < 4; wc++) {
        __syncthreads();
        for (int i = tid; i < 4096; i += 256) {
            int row = i >> 5, wl = i & 31;
            float v = g_x[pbase + (size_t)row * 128 + wc * 32 + wl];
            uint32_t hb = f2tf32(v);
            float hv = __uint_as_float(hb);
            xs_hi[wl * 133 + row] = hv;
            xs_lo[wl * 133 + row] = __uint_as_float(f2tf32(v - hv));
        }
        __syncthreads();
#pragma unroll
        for (int k8 = 0; k8 < 4; k8++) {
            const uint32_t* ah = (const uint32_t*)&xs_hi[(k8 * 8 + tig) * 133 + warp * 16 + gid];
            const uint32_t* al = (const uint32_t*)&xs_lo[(k8 * 8 + tig) * 133 + warp * 16 + gid];
            uint32_t ah0 = ah[0], ah1 = ah[8], ah2 = ah[4 * 133], ah3 = ah[4 * 133 + 8];
            uint32_t al0 = al[0], al1 = al[8], al2 = al[4 * 133], al3 = al[4 * 133 + 8];
            int kglob = wc * 32 + k8 * 8 + tig;
#pragma unroll
            for (int nf = 0; nf < 5; nf++) {
                const uint32_t* bh = (const uint32_t*)&g_TfThi[kglob * 40 + nf * 8 + gid];
                const uint32_t* bl = (const uint32_t*)&g_TfTlo[kglob * 40 + nf * 8 + gid];
                uint32_t bh0 = __ldg(bh), bh1 = __ldg(bh + 4 * 40);
                uint32_t bl0 = __ldg(bl), bl1 = __ldg(bl + 4 * 40);
                MMA_TF32(acc[nf][0], acc[nf][1], acc[nf][2], acc[nf][3],
                         ah0, ah1, ah2, ah3, bh0, bh1);
                MMA_TF32(acc[nf][0], acc[nf][1], acc[nf][2], acc[nf][3],
                         al0, al1, al2, al3, bh0, bh1);
                MMA_TF32(acc[nf][0], acc[nf][1], acc[nf][2], acc[nf][3],
                         ah0, ah1, ah2, ah3, bl0, bl1);
            }
        }
    }
    size_t row0 = (size_t)blockIdx.x * 128 + warp * 16 + gid;
#pragma unroll
    for (int nf = 0; nf < 5; nf++) {
        int n = nf * 8 + 2 * tig;
        *(float2*)&g_y1[row0 * 40 + n]       = make_float2(acc[nf][0], acc[nf][1]);
        *(float2*)&g_y1[(row0 + 8) * 40 + n] = make_float2(acc[nf][2], acc[nf][3]);
    }
}

// ---------------- fwd DFT along H: complex-packed ----------------
__global__ void __launch_bounds__(256) k_fwdH() {
    __shared__ __align__(16) float2 ysA[2560];
    __shared__ __align__(16) float2 ysB[2560];
    int tid = threadIdx.x;
    int bc = blockIdx.x;
    const float* src = g_y1 + (size_t)bc * 5120;
    for (int i = tid; i < 2560; i += 256) {
        int h = i / 20, ky = i - h * 20;
        float yr = src[h * 40 + ky], yi = src[h * 40 + 20 + ky];
        ysA[i] = make_float2(yr, yi);
        ysB[i] = make_float2(yi, -yr);
    }
    __syncthreads();
    if (tid < 200) {
        int kx0 = tid / 10, kyp = tid - (tid / 10) * 10;
        int kx1 = kx0 + 20, kyg = kyp * 2;
        u64 Z0 = pk(0.f, 0.f), Z1 = Z0, Z2 = Z0, Z3 = Z0;
#pragma unroll 4
        for (int h = 0; h < 128; h++) {
            float2 cs0 = __ldg(&g_ThP[kx0 * 128 + h]);
            float2 cs1 = __ldg(&g_ThP[kx1 * 128 + h]);
            u64 c0 = pk2(cs0.x), s0 = pk2(cs0.y);
            u64 c1 = pk2(cs1.x), s1 = pk2(cs1.y);
            ulonglong2 ya = *(const ulonglong2*)&ysA[h * 20 + kyg];
            ulonglong2 yb = *(const ulonglong2*)&ysB[h * 20 + kyg];
            fma2(Z0, ya.x, c0); fma2(Z0, yb.x, s0);
            fma2(Z1, ya.y, c0); fma2(Z1, yb.y, s0);
            fma2(Z2, ya.x, c1); fma2(Z2, yb.x, s1);
            fma2(Z3, ya.y, c1); fma2(Z3, yb.y, s1);
        }
        float zr, zi;
        size_t zb = (size_t)bc * 1600;
        unpk(Z0, zr, zi); g_z[zb + kx0 * 20 + kyg]     = zr; g_z[zb + 800 + kx0 * 20 + kyg]     = zi;
        unpk(Z1, zr, zi); g_z[zb + kx0 * 20 + kyg + 1] = zr; g_z[zb + 800 + kx0 * 20 + kyg + 1] = zi;
        unpk(Z2, zr, zi); g_z[zb + kx1 * 20 + kyg]     = zr; g_z[zb + 800 + kx1 * 20 + kyg]     = zi;
        unpk(Z3, zr, zi); g_z[zb + kx1 * 20 + kyg + 1] = zr; g_z[zb + 800 + kx1 * 20 + kyg + 1] = zi;
    }
}

// ---------------- per-mode complex channel mixing ----------------
__global__ void __launch_bounds__(256) k_mix(int layer)
{
    __shared__ __align__(16) float Wr[64 * 64], Wi[64 * 64];
    __shared__ float Zr[16 * 64], Zi[16 * 64];
    int tid = threadIdx.x;
    int mode = blockIdx.x;
    int kxi = mode / 20, ky = mode - kxi * 20;
    int q = (kxi < 20) ? 0 : 1;
    int kxm = (kxi < 20) ? kxi : kxi - 20;
    size_t col = (size_t)kxm * 20 + ky;
    const float* wrp = g_wT + (((size_t)(layer * 2 + q) * 2 + 0) * 400 + col) * 4096;
    const float* wip = g_wT + (((size_t)(layer * 2 + q) * 2 + 1) * 400 + col) * 4096;
    for (int i = tid; i < 4096; i += 256) {
        Wr[i] = wrp[i]; Wi[i] = wip[i];
    }
    int og = tid & 15, bb = tid >> 4;
    for (int pass = 0; pass < 2; pass++) {
        int b0 = pass * 16;
        __syncthreads();
        for (int i = tid; i < 1024; i += 256) {
            int lb = i >> 6, c = i & 63;
            size_t zb = ((size_t)(b0 + lb) * 64 + c) * 1600 + mode;
            Zr[i] = g_z[zb]; Zi[i] = g_z[zb + 800];
        }
        __syncthreads();
        float or0=0,or1=0,or2=0,or3=0, oi0=0,oi1=0,oi2=0,oi3=0;
#pragma unroll 8
        for (int i2 = 0; i2 < 64; i2++) {
            float zr = Zr[bb * 64 + i2], zi = Zi[bb * 64 + i2];
            float4 wr4 = *(const float4*)&Wr[i2 * 64 + og * 4];
            float4 wi4 = *(const float4*)&Wi[i2 * 64 + og * 4];
            or0 += zr * wr4.x - zi * wi4.x;  oi0 += zr * wi4.x + zi * wr4.x;
            or1 += zr * wr4.y - zi * wi4.y;  oi1 += zr * wi4.y + zi * wr4.y;
            or2 += zr * wr4.z - zi * wi4.z;  oi2 += zr * wi4.z + zi * wr4.z;
            or3 += zr * wr4.w - zi * wi4.w;  oi3 += zr * wi4.w + zi * wr4.w;
        }
        size_t ob = ((size_t)(b0 + bb) * 64 + og * 4) * 1600 + mode;
        g_zo[ob]        = or0;  g_zo[ob + 800]  = oi0;
        g_zo[ob + 1600] = or1;  g_zo[ob + 2400] = oi1;
        g_zo[ob + 3200] = or2;  g_zo[ob + 4000] = oi2;
        g_zo[ob + 4800] = or3;  g_zo[ob + 5600] = oi3;
    }
}

// ---------------- inverse DFT along H: complex-packed ----------------
__global__ void __launch_bounds__(320) k_invH() {
    __shared__ __align__(16) float2 zsA[800];
    __shared__ __align__(16) float2 zsB[800];
    int tid = threadIdx.x;
    int bo = blockIdx.x;
    for (int i = tid; i < 800; i += 320) {
        float zr = g_zo[(size_t)bo * 1600 + i];
        float zi = g_zo[(size_t)bo * 1600 + 800 + i];
        zsA[i] = make_float2(zr, zi);
        zsB[i] = make_float2(-zi, zr);
    }
    __syncthreads();
#pragma unroll
    for (int v = tid; v < 640; v += 320) {
        int h0 = v / 10, kyp = v - (v / 10) * 10;
        int h1 = h0 + 64, kyg = kyp * 2;
        u64 U00 = pk(0.f, 0.f), U01 = U00, U10 = U00, U11 = U00;
#pragma unroll 4
        for (int kx = 0; kx < 40; kx++) {
            float2 cs0 = __ldg(&g_ThP[kx * 128 + h0]);
            float2 cs1 = __ldg(&g_ThP[kx * 128 + h1]);
            u64 c0 = pk2(cs0.x), s0 = pk2(cs0.y);
            u64 c1 = pk2(cs1.x), s1 = pk2(cs1.y);
            ulonglong2 za = *(const ulonglong2*)&zsA[kx * 20 + kyg];
            ulonglong2 zb = *(const ulonglong2*)&zsB[kx * 20 + kyg];
            fma2(U00, za.x, c0); fma2(U00, zb.x, s0);
            fma2(U01, za.y, c0); fma2(U01, zb.y, s0);
            fma2(U10, za.x, c1); fma2(U10, zb.x, s1);
            fma2(U11, za.y, c1); fma2(U11, zb.y, s1);
        }
        float ur, ui;
        size_t ub = (size_t)bo * 5120;
        unpk(U00, ur, ui); g_y1[ub + h0 * 40 + kyg]     = ur; g_y1[ub + h0 * 40 + 20 + kyg]     = ui;
        unpk(U01, ur, ui); g_y1[ub + h0 * 40 + kyg + 1] = ur; g_y1[ub + h0 * 40 + 20 + kyg + 1] = ui;
        unpk(U10, ur, ui); g_y1[ub + h1 * 40 + kyg]     = ur; g_y1[ub + h1 * 40 + 20 + kyg]     = ui;
        unpk(U11, ur, ui); g_y1[ub + h1 * 40 + kyg + 1] = ur; g_y1[ub + h1 * 40 + 20 + kyg + 1] = ui;
    }
}

// ---------------- inverse rfft along W via tf32 MMA (3-term split) ----------------
__global__ void __launch_bounds__(256) k_invW_mma() {
    __shared__ float us_hi[40 * 133], us_lo[40 * 133];
    int tid = threadIdx.x;
    int lane = tid & 31, warp = tid >> 5;
    int tig = lane & 3, gid = lane >> 2;
    int bo = blockIdx.x;
    const float* ub = g_y1 + (size_t)bo * 5120;
    for (int i = tid; i < 5120; i += 256) {
        int h = i / 40, k = i - h * 40;
        float v = ub[i];
        uint32_t hb = f2tf32(v);
        float hv = __uint_as_float(hb);
        us_hi[k * 133 + h] = hv;
        us_lo[k * 133 + h] = __uint_as_float(f2tf32(v - hv));
    }
    __syncthreads();
    float acc[16][4];
#pragma unroll
    for (int nf = 0; nf < 16; nf++)
#pragma unroll
        for (int r = 0; r < 4; r++) acc[nf][r] = 0.f;
#pragma unroll
    for (int k8 = 0; k8 < 5; k8++) {
        int k = k8 * 8 + tig;
        const uint32_t* ah = (const uint32_t*)&us_hi[k * 133 + warp * 16 + gid];
        const uint32_t* al = (const uint32_t*)&us_lo[k * 133 + warp * 16 + gid];
        uint32_t ah0 = ah[0], ah1 = ah[8], ah2 = ah[4 * 133], ah3 = ah[4 * 133 + 8];
        uint32_t al0 = al[0], al1 = al[8], al2 = al[4 * 133], al3 = al[4 * 133 + 8];
#pragma unroll
        for (int nf = 0; nf < 16; nf++) {
            const uint32_t* bh = (const uint32_t*)&g_Ghi[k * 128 + nf * 8 + gid];
            const uint32_t* bl = (const uint32_t*)&g_Glo[k * 128 + nf * 8 + gid];
            uint32_t bh0 = __ldg(bh), bh1 = __ldg(bh + 4 * 128);
            uint32_t bl0 = __ldg(bl), bl1 = __ldg(bl + 4 * 128);
            MMA_TF32(acc[nf][0], acc[nf][1], acc[nf][2], acc[nf][3],
                     ah0, ah1, ah2, ah3, bh0, bh1);
            MMA_TF32(acc[nf][0], acc[nf][1], acc[nf][2], acc[nf][3],
                     al0, al1, al2, al3, bh0, bh1);
            MMA_TF32(acc[nf][0], acc[nf][1], acc[nf][2], acc[nf][3],
                     ah0, ah1, ah2, ah3, bl0, bl1);
        }
    }
    float* xo = g_x1 + (size_t)bo * NPIX;
    int h = warp * 16 + gid;
#pragma unroll
    for (int nf = 0; nf < 16; nf++) {
        int n = nf * 8 + 2 * tig;
        *(float2*)&xo[(size_t)h * 128 + n]       = make_float2(acc[nf][0], acc[nf][1]);
        *(float2*)&xo[(size_t)(h + 8) * 128 + n] = make_float2(acc[nf][2], acc[nf][3]);
    }
}

// ---------------- conv3x3 via tf32 tensor cores ----------------
#define CONV_TS_ELEMS (16 * 524)
#define CONV_WS_ELEMS (144 * 66)
#define CONV_SMEM_BYTES ((CONV_TS_ELEMS + CONV_WS_ELEMS) * 4)

__global__ void __launch_bounds__(256) k_conv_mma(const float* __restrict__ cb, int layer)
{
    extern __shared__ float sm[];
    float* ts = sm;
    float* wsh = sm + CONV_TS_ELEMS;
    int tid = threadIdx.x;
    int lane = tid & 31, warp = tid >> 5;
    int warpM = warp & 3, warpN = warp >> 2;
    int tig = lane & 3, gid = lane >> 2;
    int b = blockIdx.y;
    int h0 = blockIdx.x * 2;
    const float* xin = g_x + (size_t)b * 64 * NPIX;
    const float* cwT = g_cwT + (size_t)layer * 9 * 4096;

    float acc[4][4][4];
#pragma unroll
    for (int nf = 0; nf < 4; nf++) {
        int o = warpN * 32 + nf * 8 + 2 * tig;
        float bb0 = __ldg(&cb[layer * 64 + o]);
        float bb1 = __ldg(&cb[layer * 64 + o + 1]);
#pragma unroll
        for (int mf = 0; mf < 4; mf++) {
            acc[mf][nf][0] = bb0; acc[mf][nf][1] = bb1;
            acc[mf][nf][2] = bb0; acc[mf][nf][3] = bb1;
        }
    }

    for (int chunk = 0; chunk < 4; chunk++) {
        int c0 = chunk * 16;
        __syncthreads();
        for (int i = tid; i < 16 * 4 * 131; i += 256) {
            int cc = i / 524; int rem = i - cc * 524;
            int rr = rem / 131; int ww = rem - rr * 131;
            int gh = (h0 + rr - 1) & 127;
            int gw = (ww - 1) & 127;
            float v = xin[(size_t)(c0 + cc) * NPIX + gh * 128 + gw];
            ts[i] = __uint_as_float(f2tf32(v));
        }
        for (int i = tid; i < 9216; i += 256) {
            int t9 = i >> 10; int rem = i & 1023;
            int kg = rem >> 6; int o = rem & 63;
            wsh[(t9 * 16 + kg) * 66 + o] = cwT[(size_t)t9 * 4096 + (c0 + kg) * 64 + o];
        }
        __syncthreads();
#pragma unroll
        for (int tap = 0; tap < 9; tap++) {
            int dy = tap / 3, dx = tap - 3 * dy;
#pragma unroll
            for (int k8 = 0; k8 < 2; k8++) {
                uint32_t bfr[4][2];
                const uint32_t* wp = (const uint32_t*)&wsh[(tap * 16 + k8 * 8 + tig) * 66 + warpN * 32 + gid];
#pragma unroll
                for (int nf = 0; nf < 4; nf++) {
                    bfr[nf][0] = wp[nf * 8];
                    bfr[nf][1] = wp[nf * 8 + 4 * 66];
                }
#pragma unroll
                for (int mf = 0; mf < 4; mf++) {
                    int pbase = warpM * 64 + mf * 16;
                    int row = (pbase >> 7) + dy;
                    int wb = (pbase & 127) + gid + dx;
                    const uint32_t* ap = (const uint32_t*)&ts[(k8 * 8 + tig) * 524 + row * 131 + wb];
                    uint32_t a0 = ap[0], a1 = ap[8], a2 = ap[4 * 524], a3 = ap[4 * 524 + 8];
#pragma unroll
                    for (int nf = 0; nf < 4; nf++) {
                        MMA_TF32(acc[mf][nf][0], acc[mf][nf][1], acc[mf][nf][2], acc[mf][nf][3],
                                 a0, a1, a2, a3, bfr[nf][0], bfr[nf][1]);
                    }
                }
            }
        }
    }
    size_t obase = ((size_t)b * 64) * NPIX + (size_t)h0 * 128;
#pragma unroll
    for (int mf = 0; mf < 4; mf++) {
        int p_lo = warpM * 64 + mf * 16 + gid;
#pragma unroll
        for (int nf = 0; nf < 4; nf++) {
            int o = warpN * 32 + nf * 8 + 2 * tig;
            float* dst = g_x2 + obase + (size_t)o * NPIX;
            dst[p_lo]            = acc[mf][nf][0];
            dst[NPIX + p_lo]     = acc[mf][nf][1];
            dst[p_lo + 8]        = acc[mf][nf][2];
            dst[NPIX + p_lo + 8] = acc[mf][nf][3];
        }
    }
}

// ---------------- products + pointwise mix + tanh residual (FFMA2) ----------------
__global__ void __launch_bounds__(256) k_combine(
    const float* __restrict__ pw, const float* __restrict__ pb, int layer)
{
    __shared__ __align__(16) float wst[130 * 68];
    __shared__ float bs[64];
    int tid = threadIdx.x;
    for (int i = tid; i < 8320; i += 256) {
        int o = i / 130, c = i - o * 130;
        wst[c * 68 + o] = pw[(size_t)layer * 8320 + i];
    }
    if (tid < 64) bs[tid] = pb[layer * 64 + tid];
    __syncthreads();
    int po = tid & 127, oh = tid >> 7, ob = oh * 32;
    int p0 = blockIdx.x * 256 + po;
    int b = p0 >> 14, pix0 = p0 & 16383;
    const float* x1p = g_x1 + ((size_t)b * 64) * NPIX + pix0;
    const float* x2p = g_x2 + ((size_t)b * 64) * NPIX + pix0;
    u64 acc0[16], acc1[16];
#pragma unroll
    for (int q = 0; q < 16; q++) {
        u64 v = pk(bs[ob + 2 * q], bs[ob + 2 * q + 1]);
        acc0[q] = v; acc1[q] = v;
    }
#pragma unroll 4
    for (int c = 0; c < 64; c++) {
        u64 A0 = pk2(x1p[(size_t)c * NPIX]);
        u64 A1 = pk2(x1p[(size_t)c * NPIX + 128]);
        u64 D0 = pk2(x2p[(size_t)c * NPIX]);
        u64 D1 = pk2(x2p[(size_t)c * NPIX + 128]);
        const float* wa = &wst[c * 68 + ob];
        const float* wd = &wst[(64 + c) * 68 + ob];
#pragma unroll
        for (int q8 = 0; q8 < 8; q8++) {
            ulonglong2 wva = *(const ulonglong2*)&wa[q8 * 4];
            fma2(acc0[q8 * 2],     wva.x, A0); fma2(acc0[q8 * 2 + 1], wva.y, A0);
            fma2(acc1[q8 * 2],     wva.x, A1); fma2(acc1[q8 * 2 + 1], wva.y, A1);
            ulonglong2 wvd = *(const ulonglong2*)&wd[q8 * 4];
            fma2(acc0[q8 * 2],     wvd.x, D0); fma2(acc0[q8 * 2 + 1], wvd.y, D0);
            fma2(acc1[q8 * 2],     wvd.x, D1); fma2(acc1[q8 * 2 + 1], wvd.y, D1);
        }
    }
    float p00 = x1p[0] * x1p[(size_t)2 * NPIX];
    float p01 = x1p[(size_t)1 * NPIX] * x1p[(size_t)3 * NPIX];
    float p10 = x1p[128] * x1p[(size_t)2 * NPIX + 128];
    float p11 = x1p[(size_t)1 * NPIX + 128] * x1p[(size_t)3 * NPIX + 128];
    {
        u64 P00 = pk2(p00), P01 = pk2(p01), P10 = pk2(p10), P11 = pk2(p11);
        const float* w0r = &wst[128 * 68 + ob];
        const float* w1r = &wst[129 * 68 + ob];
#pragma unroll
        for (int q8 = 0; q8 < 8; q8++) {
            ulonglong2 w0v = *(const ulonglong2*)&w0r[q8 * 4];
            ulonglong2 w1v = *(const ulonglong2*)&w1r[q8 * 4];
            fma2(acc0[q8 * 2],     w0v.x, P00); fma2(acc0[q8 * 2 + 1], w0v.y, P00);
            fma2(acc0[q8 * 2],     w1v.x, P01); fma2(acc0[q8 * 2 + 1], w1v.y, P01);
            fma2(acc1[q8 * 2],     w0v.x, P10); fma2(acc1[q8 * 2 + 1], w0v.y, P10);
            fma2(acc1[q8 * 2],     w1v.x, P11); fma2(acc1[q8 * 2 + 1], w1v.y, P11);
        }
    }
    float* xp = g_x + ((size_t)b * 64 + ob) * NPIX + pix0;
#pragma unroll
    for (int q = 0; q < 16; q++) {
        float lo, hi;
        unpk(acc0[q], lo, hi);
        xp[(size_t)(2 * q) * NPIX]           += tanhf(lo);
        xp[(size_t)(2 * q + 1) * NPIX]       += tanhf(hi);
        unpk(acc1[q], lo, hi);
        xp[(size_t)(2 * q) * NPIX + 128]     += tanhf(lo);
        xp[(size_t)(2 * q + 1) * NPIX + 128] += tanhf(hi);
    }
}

// ---------------- final projection MLP: 2 pixels/thread ----------------
__global__ void __launch_bounds__(128) k_final(
    const float* __restrict__ w1, const float* __restrict__ b1,
    const float* __restrict__ w2, const float* __restrict__ b2,
    float* __restrict__ out)
{
    __shared__ __align__(16) float w1s[128 * 64];
    __shared__ float b1s[128], w2s[128];
    int tid = threadIdx.x;
    for (int i = tid; i < 8192; i += 128) w1s[i] = w1[i];
    b1s[tid] = b1[tid];
    w2s[tid] = w2[tid];
    __syncthreads();
    int p0 = blockIdx.x * 256 + tid;
    int b = p0 >> 14, pix0 = p0 & 16383;
    const float* xp = g_x + ((size_t)b * 64) * NPIX + pix0;
    u64 xv0[32], xv1[32];
#pragma unroll
    for (int c = 0; c < 32; c++) {
        xv0[c] = pk(xp[(size_t)(2 * c) * NPIX],       xp[(size_t)(2 * c + 1) * NPIX]);
        xv1[c] = pk(xp[(size_t)(2 * c) * NPIX + 128], xp[(size_t)(2 * c + 1) * NPIX + 128]);
    }
    float acc0 = b2[0], acc1 = acc0;
    for (int m = 0; m < 128; m++) {
        u64 a0 = pk(0.f, 0.f), a1 = a0, b0 = a0, b1v = a0;
        const float* wr = &w1s[m * 64];
#pragma unroll
        for (int q = 0; q < 16; q++) {
            ulonglong2 wv = *(const ulonglong2*)&wr[q * 4];
            if ((q & 1) == 0) {
                fma2(a0, wv.x, xv0[q * 2]); fma2(a1, wv.y, xv0[q * 2 + 1]);
                fma2(b0, wv.x, xv1[q * 2]); fma2(b1v, wv.y, xv1[q * 2 + 1]);
            } else {
                fma2(a0, wv.x, xv0[q * 2]); fma2(a1, wv.y, xv0[q * 2 + 1]);
                fma2(b0, wv.x, xv1[q * 2]); fma2(b1v, wv.y, xv1[q * 2 + 1]);
            }
        }
        float l0, h0, l1, h1;
        unpk(a0, l0, h0); unpk(a1, l1, h1);
        float t0 = b1s[m] + ((l0 + h0) + (l1 + h1));
        unpk(b0, l0, h0); unpk(b1v, l1, h1);
        float t1 = b1s[m] + ((l0 + h0) + (l1 + h1));
        acc0 += w2s[m] * gelu_t(t0);
        acc1 += w2s[m] * gelu_t(t1);
    }
    out[p0] = acc0;
    out[p0 + 128] = acc1;
}

// ---------------- launch ----------------
extern "C" void kernel_launch(void* const* d_in, const int* in_sizes, int n_in,
                              void* d_out, int out_size)
{
    const float* x      = (const float*)d_in[0];
    const float* qa     = (const float*)d_in[1];
    const float* qb     = (const float*)d_in[2];
    const float* fc0_w1 = (const float*)d_in[3];
    const float* fc0_b1 = (const float*)d_in[4];
    const float* fc0_w2 = (const float*)d_in[5];
    const float* fc0_b2 = (const float*)d_in[6];
    const float* sw1r   = (const float*)d_in[7];
    const float* sw1i   = (const float*)d_in[8];
    const float* sw2r   = (const float*)d_in[9];
    const float* sw2i   = (const float*)d_in[10];
    const float* cw     = (const float*)d_in[11];
    const float* cb     = (const float*)d_in[12];
    const float* pw     = (const float*)d_in[13];
    const float* pb     = (const float*)d_in[14];
    const float* fc1_w1 = (const float*)d_in[15];
    const float* fc1_b1 = (const float*)d_in[16];
    const float* fc1_w2 = (const float*)d_in[17];
    const float* fc1_b2 = (const float*)d_in[18];
    float* out = (float*)d_out;

    static cudaStream_t s2 = nullptr;
    static cudaEvent_t evFork = nullptr, evJoin = nullptr, evPro = nullptr;
    if (!s2) {
        cudaFuncSetAttribute(k_conv_mma, cudaFuncAttributeMaxDynamicSharedMemorySize, CONV_SMEM_BYTES);
        cudaStreamCreateWithFlags(&s2, cudaStreamNonBlocking);
        cudaEventCreateWithFlags(&evFork, cudaEventDisableTiming);
        cudaEventCreateWithFlags(&evJoin, cudaEventDisableTiming);
        cudaEventCreateWithFlags(&evPro, cudaEventDisableTiming);
    }

    // prolog: table/weight prep on s2 concurrent with lift on stream 0
    cudaEventRecord(evFork, 0);                    // order s2 after capture start
    cudaStreamWaitEvent(s2, evFork, 0);
    k_init_tables<<<20, 256, 0, s2>>>();
    k_wt<<<dim3(13, 128, 16), dim3(32, 8), 0, s2>>>(sw1r, sw1i, sw2r, sw2i);
    k_cwt<<<(147456 + 255) / 256, 256, 0, s2>>>(cw);
    cudaEventRecord(evPro, s2);

    k_lift<<<2048, 128>>>(x, qa, qb, fc0_w1, fc0_b1, fc0_w2, fc0_b2);
    cudaStreamWaitEvent(0, evPro, 0);              // tables ready before spectral chain

    for (int layer = 0; layer < 4; layer++) {
        cudaEventRecord(evFork, 0);
        cudaStreamWaitEvent(s2, evFork, 0);
        k_conv_mma<<<dim3(64, 32), 256, CONV_SMEM_BYTES, s2>>>(cb, layer);
        cudaEventRecord(evJoin, s2);

        k_fwdW_mma<<<2048, 256>>>();
        k_fwdH<<<2048, 256>>>();
        k_mix<<<800, 256>>>(layer);
        k_invH<<<2048, 320>>>();
        k_invW_mma<<<2048, 256>>>();

        cudaStreamWaitEvent(0, evJoin, 0);
        k_combine<<<2048, 256>>>(pw, pb, layer);
    }

    k_final<<<2048, 128>>>(fc1_w1, fc1_b1, fc1_w2, fc1_b2, out);
}